// round 7
// baseline (speedup 1.0000x reference)
#include <cuda_runtime.h>
#include <cstdint>

// Problem constants
#define Bsz 4
#define Ssz 2048
#define Hn  16
#define DKk 64
#define Dm  1024
#define Mrows (Bsz*Ssz)   // 8192

// ---------------- scratch (__device__ globals) ------------------------------
__device__ __align__(1024) float g_Q[(size_t)Bsz*Hn*Ssz*DKk];     // [B,H,S,dk] tf32-rounded
__device__ __align__(1024) float g_K[(size_t)Bsz*Hn*Ssz*DKk];
__device__ __align__(1024) float g_V[(size_t)Bsz*Hn*Ssz*DKk];
__device__ __align__(1024) float g_attn[(size_t)Mrows*Dm];        // [B*S, D] tf32-rounded
__device__ __align__(1024) float g_Xq[(size_t)Mrows*Dm];
__device__ __align__(1024) float g_Xk[(size_t)Mrows*Dm];
__device__ __align__(1024) float g_Xv[(size_t)Mrows*Dm];
__device__ __align__(1024) float g_Wq[(size_t)Dm*Dm];
__device__ __align__(1024) float g_Wk[(size_t)Dm*Dm];
__device__ __align__(1024) float g_Wv[(size_t)Dm*Dm];
__device__ __align__(1024) float g_Wo[(size_t)Dm*Dm];

// ---------------- helpers ----------------------------------------------------
__device__ __forceinline__ uint32_t smem_u32(const void* p) {
    uint32_t a;
    asm("{ .reg .u64 t; cvta.to.shared.u64 t, %1; cvt.u32.u64 %0, t; }" : "=r"(a) : "l"(p));
    return a;
}
__device__ __forceinline__ void cp_async16(uint32_t dst, const void* src) {
    asm volatile("cp.async.cg.shared.global [%0], [%1], 16;" :: "r"(dst), "l"(src));
}
#define CP_COMMIT() asm volatile("cp.async.commit_group;" ::: "memory")
#define CP_WAIT0()  asm volatile("cp.async.wait_group 0;" ::: "memory")
#define CP_WAIT1()  asm volatile("cp.async.wait_group 1;" ::: "memory")

__device__ __forceinline__ float tf32_rn(float x) {
    uint32_t u;
    asm("cvt.rna.tf32.f32 %0, %1;" : "=r"(u) : "f"(x));
    return __uint_as_float(u);
}
__device__ __forceinline__ void mma_tf32(float* c, const uint32_t* a, uint32_t b0, uint32_t b1) {
    asm volatile(
        "mma.sync.aligned.m16n8k8.row.col.f32.tf32.tf32.f32 "
        "{%0,%1,%2,%3}, {%4,%5,%6,%7}, {%8,%9}, {%0,%1,%2,%3};"
        : "+f"(c[0]), "+f"(c[1]), "+f"(c[2]), "+f"(c[3])
        : "r"(a[0]), "r"(a[1]), "r"(a[2]), "r"(a[3]), "r"(b0), "r"(b1));
}

// ---------------------------------------------------------------------------
// mma.sync tf32 NT GEMM, 3-stage cp.async pipeline (unchanged).
// ---------------------------------------------------------------------------
#define LDA 36
#define GEMM_SMEM_BYTES (6 * 4608 * 4)

__device__ __forceinline__ void gemm_mma_body(const float* __restrict__ X,
                                              const float* __restrict__ W,
                                              const float* __restrict__ bias,
                                              float* __restrict__ out,
                                              int layout)
{
    extern __shared__ float sm[];
    float* Abuf[3] = { sm,             sm + 4608,      sm + 2 * 4608 };
    float* Bbuf[3] = { sm + 3 * 4608,  sm + 4 * 4608,  sm + 5 * 4608 };

    const int tid  = threadIdx.x;
    const int lane = tid & 31, wid = tid >> 5;
    const int wm   = wid >> 2, wn = wid & 3;
    const int g    = lane >> 2, q = lane & 3;
    const int bm   = blockIdx.y * 128;
    const int bn   = blockIdx.x * 128;

    float acc[4][4][4];
#pragma unroll
    for (int i = 0; i < 4; i++)
#pragma unroll
        for (int j = 0; j < 4; j++)
#pragma unroll
            for (int k = 0; k < 4; k++) acc[i][j][k] = 0.f;

    auto issue_tile = [&](int kt, int buf) {
#pragma unroll
        for (int i = 0; i < 4; i++) {
            int idx = i * 256 + tid;
            int r = idx >> 3, c4 = idx & 7;
            cp_async16(smem_u32(&Abuf[buf][r * LDA + c4 * 4]),
                       X + (size_t)(bm + r) * Dm + kt * 32 + c4 * 4);
        }
#pragma unroll
        for (int i = 0; i < 4; i++) {
            int idx = i * 256 + tid;
            int r = idx >> 3, c4 = idx & 7;
            cp_async16(smem_u32(&Bbuf[buf][r * LDA + c4 * 4]),
                       W + (size_t)(bn + r) * Dm + kt * 32 + c4 * 4);
        }
        CP_COMMIT();
    };

    const int NT = Dm / 32;
    issue_tile(0, 0);
    issue_tile(1, 1);

    int buf = 0;
    for (int kt = 0; kt < NT; kt++) {
        if (kt + 1 < NT) { CP_WAIT1(); } else { CP_WAIT0(); }
        __syncthreads();
        if (kt + 2 < NT) {
            int nb = buf + 2; if (nb >= 3) nb -= 3;
            issue_tile(kt + 2, nb);
        }

        const float* Ab = Abuf[buf];
        const float* Bb = Bbuf[buf];
#pragma unroll
        for (int ks = 0; ks < 4; ks++) {
            uint32_t afr[4][4], bfr[4][2];
#pragma unroll
            for (int mt = 0; mt < 4; mt++) {
                const float* pa = Ab + (wm * 64 + mt * 16 + g) * LDA + ks * 8 + q;
                afr[mt][0] = __float_as_uint(pa[0]);
                afr[mt][1] = __float_as_uint(pa[8 * LDA]);
                afr[mt][2] = __float_as_uint(pa[4]);
                afr[mt][3] = __float_as_uint(pa[8 * LDA + 4]);
            }
#pragma unroll
            for (int nt = 0; nt < 4; nt++) {
                const float* pb = Bb + (wn * 32 + nt * 8 + g) * LDA + ks * 8 + q;
                bfr[nt][0] = __float_as_uint(pb[0]);
                bfr[nt][1] = __float_as_uint(pb[4]);
            }
#pragma unroll
            for (int mt = 0; mt < 4; mt++)
#pragma unroll
                for (int nt = 0; nt < 4; nt++)
                    mma_tf32(acc[mt][nt], afr[mt], bfr[nt][0], bfr[nt][1]);
        }
        __syncthreads();
        buf = buf + 1; if (buf >= 3) buf = 0;
    }

#pragma unroll
    for (int mt = 0; mt < 4; mt++) {
        int r0 = bm + wm * 64 + mt * 16 + g;
#pragma unroll
        for (int nt = 0; nt < 4; nt++) {
            int n = bn + wn * 32 + nt * 8 + q * 2;
            float2 v0, v1;
            if (layout) {
                v0.x = tf32_rn(acc[mt][nt][0] + bias[n]);
                v0.y = tf32_rn(acc[mt][nt][1] + bias[n + 1]);
                v1.x = tf32_rn(acc[mt][nt][2] + bias[n]);
                v1.y = tf32_rn(acc[mt][nt][3] + bias[n + 1]);
                int h = n >> 6, d = n & 63;
                int b0i = r0 >> 11, s0 = r0 & (Ssz - 1);
                int r1 = r0 + 8;
                int b1i = r1 >> 11, s1 = r1 & (Ssz - 1);
                *(float2*)&out[((size_t)((b0i * Hn + h) * Ssz + s0)) * DKk + d] = v0;
                *(float2*)&out[((size_t)((b1i * Hn + h) * Ssz + s1)) * DKk + d] = v1;
            } else {
                v0.x = acc[mt][nt][0] + bias[n];
                v0.y = acc[mt][nt][1] + bias[n + 1];
                v1.x = acc[mt][nt][2] + bias[n];
                v1.y = acc[mt][nt][3] + bias[n + 1];
                *(float2*)&out[(size_t)r0 * Dm + n] = v0;
                *(float2*)&out[(size_t)(r0 + 8) * Dm + n] = v1;
            }
        }
    }
}

__global__ __launch_bounds__(256, 2) void gemm_qkv_tc(const float* __restrict__ bq,
                                                      const float* __restrict__ bk,
                                                      const float* __restrict__ bv)
{
    const float* X; const float* W; const float* bias; float* out;
    if (blockIdx.z == 0)      { X = g_Xq; W = g_Wq; bias = bq; out = g_Q; }
    else if (blockIdx.z == 1) { X = g_Xk; W = g_Wk; bias = bk; out = g_K; }
    else                      { X = g_Xv; W = g_Wv; bias = bv; out = g_V; }
    gemm_mma_body(X, W, bias, out, 1);
}

__global__ __launch_bounds__(256, 2) void gemm_out_tc(const float* __restrict__ bo,
                                                      float* __restrict__ out)
{
    gemm_mma_body(g_attn, g_Wo, bo, out, 0);
}

// ---------------------------------------------------------------------------
// Fused tf32 RN pre-rounding
// ---------------------------------------------------------------------------
__global__ __launch_bounds__(256) void round_x3(const float* __restrict__ xq,
                                                const float* __restrict__ xk,
                                                const float* __restrict__ xv)
{
    const float* s; float* d;
    if (blockIdx.z == 0)      { s = xq; d = g_Xq; }
    else if (blockIdx.z == 1) { s = xk; d = g_Xk; }
    else                      { s = xv; d = g_Xv; }
    int i = blockIdx.x * blockDim.x + threadIdx.x;
    float4 v = ((const float4*)s)[i];
    float4 o;
    o.x = tf32_rn(v.x); o.y = tf32_rn(v.y);
    o.z = tf32_rn(v.z); o.w = tf32_rn(v.w);
    ((float4*)d)[i] = o;
}

__global__ __launch_bounds__(256) void round_w4(const float* __restrict__ wq,
                                                const float* __restrict__ wk,
                                                const float* __restrict__ wv,
                                                const float* __restrict__ wo)
{
    const float* s; float* d;
    if (blockIdx.z == 0)      { s = wq; d = g_Wq; }
    else if (blockIdx.z == 1) { s = wk; d = g_Wk; }
    else if (blockIdx.z == 2) { s = wv; d = g_Wv; }
    else                      { s = wo; d = g_Wo; }
    int i = blockIdx.x * blockDim.x + threadIdx.x;
    float4 v = ((const float4*)s)[i];
    float4 o;
    o.x = tf32_rn(v.x); o.y = tf32_rn(v.y);
    o.z = tf32_rn(v.z); o.w = tf32_rn(v.w);
    ((float4*)d)[i] = o;
}

// ---------------------------------------------------------------------------
// Flash attention, mma.sync tf32.
// CTA = 128 q-rows x bh, 8 warps (256 thr), warp owns 16 rows.
// Occupancy-focused: ~<=128 regs/thread, 2 CTA/SM -> 16 warps/SM.
// K/V double-buffered cp.async; same math order as R6 (bit-identical output).
// ---------------------------------------------------------------------------
#define LDK 68
#define TILE_F (64 * LDK)
#define ATT_SMEM ((4 * TILE_F + 128 * LDK) * 4)   // K x2, V x2, Ps[128] = 104448 B

__global__ __launch_bounds__(256, 2) void attn_mma_kernel()
{
    extern __shared__ float smf[];
    float* Kbuf[2] = { smf,              smf + TILE_F };
    float* Vbuf[2] = { smf + 2 * TILE_F, smf + 3 * TILE_F };
    float* Ps      =   smf + 4 * TILE_F;   // [128][LDK]

    const int bh = blockIdx.y;
    const int qb = blockIdx.x * 128;
    const int tid = threadIdx.x;
    const int lane = tid & 31, w = tid >> 5;       // w: 0..7
    const int g = lane >> 2, q = lane & 3;

    const float* Qb = g_Q + (size_t)bh * Ssz * DKk;
    const float* Kb = g_K + (size_t)bh * Ssz * DKk;
    const float* Vb = g_V + (size_t)bh * Ssz * DKk;

    // ---- stage Q tile (128 rows, scaled 1/8) into Ps, grab fragments ------
#pragma unroll
    for (int i = 0; i < 8; i++) {
        int idx = i * 256 + tid;
        int r = idx >> 4, c = (idx & 15) * 4;
        float4 v = *(const float4*)&Qb[(size_t)(qb + r) * DKk + c];
        v.x *= 0.125f; v.y *= 0.125f; v.z *= 0.125f; v.w *= 0.125f;
        *(float4*)&Ps[r * LDK + c] = v;
    }
    __syncthreads();

    uint32_t qfr[8][4];
#pragma unroll
    for (int ks = 0; ks < 8; ks++) {
        const float* pa = &Ps[(w * 16 + g) * LDK + ks * 8 + q];
        qfr[ks][0] = __float_as_uint(pa[0]);
        qfr[ks][1] = __float_as_uint(pa[8 * LDK]);
        qfr[ks][2] = __float_as_uint(pa[4]);
        qfr[ks][3] = __float_as_uint(pa[8 * LDK + 4]);
    }
    __syncthreads();   // Ps free for reuse

    auto issue_kv = [&](int kt, int bufi) {
        const float* Kp = Kb + (size_t)(kt * 64) * DKk;
        const float* Vp = Vb + (size_t)(kt * 64) * DKk;
        float* kd = Kbuf[bufi];
        float* vd = Vbuf[bufi];
#pragma unroll
        for (int i = 0; i < 4; i++) {
            int idx = i * 256 + tid;
            int r = idx >> 4, c = (idx & 15) * 4;
            cp_async16(smem_u32(&kd[r * LDK + c]), &Kp[r * DKk + c]);
            cp_async16(smem_u32(&vd[r * LDK + c]), &Vp[r * DKk + c]);
        }
        CP_COMMIT();
    };

    float oacc[8][4];
#pragma unroll
    for (int nt = 0; nt < 8; nt++)
#pragma unroll
        for (int k = 0; k < 4; k++) oacc[nt][k] = 0.f;
    float mA = -1e30f, mB = -1e30f, lA = 0.f, lB = 0.f;

    const int NT = Ssz / 64;
    issue_kv(0, 0);

    for (int kt = 0; kt < NT; kt++) {
        const int buf = kt & 1;
        if (kt + 1 < NT) {
            issue_kv(kt + 1, buf ^ 1);
            CP_WAIT1();
        } else {
            CP_WAIT0();
        }
        __syncthreads();

        const float* Ks = Kbuf[buf];
        const float* Vs = Vbuf[buf];

        // ---- S = Q K^T : warp computes 16 x 64 ----
        float sacc[8][4];
#pragma unroll
        for (int nt = 0; nt < 8; nt++)
#pragma unroll
            for (int k = 0; k < 4; k++) sacc[nt][k] = 0.f;
#pragma unroll
        for (int nt = 0; nt < 8; nt++) {
#pragma unroll
            for (int ks = 0; ks < 8; ks++) {
                const float* pb = &Ks[(nt * 8 + g) * LDK + ks * 8 + q];
                mma_tf32(sacc[nt], qfr[ks],
                         __float_as_uint(pb[0]), __float_as_uint(pb[4]));
            }
        }

        // ---- online softmax (rows g and g+8 per thread) ----
        float mtA = -1e30f, mtB = -1e30f;
#pragma unroll
        for (int nt = 0; nt < 8; nt++) {
            mtA = fmaxf(mtA, fmaxf(sacc[nt][0], sacc[nt][1]));
            mtB = fmaxf(mtB, fmaxf(sacc[nt][2], sacc[nt][3]));
        }
        mtA = fmaxf(mtA, __shfl_xor_sync(0xffffffffu, mtA, 1));
        mtA = fmaxf(mtA, __shfl_xor_sync(0xffffffffu, mtA, 2));
        mtB = fmaxf(mtB, __shfl_xor_sync(0xffffffffu, mtB, 1));
        mtB = fmaxf(mtB, __shfl_xor_sync(0xffffffffu, mtB, 2));

        float mnA = fmaxf(mA, mtA), mnB = fmaxf(mB, mtB);
        float corrA = __expf(mA - mnA), corrB = __expf(mB - mnB);
        mA = mnA; mB = mnB;

        float sA = 0.f, sB = 0.f;
        float* prowA = &Ps[(w * 16 + g) * LDK];
        float* prowB = &Ps[(w * 16 + g + 8) * LDK];
#pragma unroll
        for (int nt = 0; nt < 8; nt++) {
            float p0 = __expf(sacc[nt][0] - mA);
            float p1 = __expf(sacc[nt][1] - mA);
            float p2 = __expf(sacc[nt][2] - mB);
            float p3 = __expf(sacc[nt][3] - mB);
            sA += p0 + p1;
            sB += p2 + p3;
            float2 vA = { tf32_rn(p0), tf32_rn(p1) };
            float2 vB = { tf32_rn(p2), tf32_rn(p3) };
            *(float2*)&prowA[nt * 8 + q * 2] = vA;
            *(float2*)&prowB[nt * 8 + q * 2] = vB;
        }
        sA += __shfl_xor_sync(0xffffffffu, sA, 1);
        sA += __shfl_xor_sync(0xffffffffu, sA, 2);
        sB += __shfl_xor_sync(0xffffffffu, sB, 1);
        sB += __shfl_xor_sync(0xffffffffu, sB, 2);
        lA = lA * corrA + sA;
        lB = lB * corrB + sB;

#pragma unroll
        for (int nt = 0; nt < 8; nt++) {
            oacc[nt][0] *= corrA; oacc[nt][1] *= corrA;
            oacc[nt][2] *= corrB; oacc[nt][3] *= corrB;
        }
        __syncwarp();

        // ---- O += P * V  (B fragments from untransposed Vs) ----
#pragma unroll
        for (int ks = 0; ks < 8; ks++) {
            uint32_t afr[4];
            const float* pa = &Ps[(w * 16 + g) * LDK + ks * 8 + q];
            afr[0] = __float_as_uint(pa[0]);
            afr[1] = __float_as_uint(pa[8 * LDK]);
            afr[2] = __float_as_uint(pa[4]);
            afr[3] = __float_as_uint(pa[8 * LDK + 4]);
#pragma unroll
            for (int nt = 0; nt < 8; nt++) {
                const uint32_t b0 = __float_as_uint(Vs[(ks * 8 + q) * LDK + nt * 8 + g]);
                const uint32_t b1 = __float_as_uint(Vs[(ks * 8 + q + 4) * LDK + nt * 8 + g]);
                mma_tf32(oacc[nt], afr, b0, b1);
            }
        }
        __syncthreads();
    }

    // ---- epilogue ----------------------------------------------------------
    float invA = 1.f / lA, invB = 1.f / lB;
    int b = bh >> 4, h = bh & 15;
    int row0 = qb + w * 16 + g;
    int row1 = row0 + 8;
#pragma unroll
    for (int nt = 0; nt < 8; nt++) {
        int col = h * DKk + nt * 8 + q * 2;
        float2 v0 = { tf32_rn(oacc[nt][0] * invA), tf32_rn(oacc[nt][1] * invA) };
        float2 v1 = { tf32_rn(oacc[nt][2] * invB), tf32_rn(oacc[nt][3] * invB) };
        *(float2*)&g_attn[(size_t)(b * Ssz + row0) * Dm + col] = v0;
        *(float2*)&g_attn[(size_t)(b * Ssz + row1) * Dm + col] = v1;
    }
}

// ---------------------------------------------------------------------------
extern "C" void kernel_launch(void* const* d_in, const int* in_sizes, int n_in,
                              void* d_out, int out_size)
{
    const float* query = (const float*)d_in[0];
    const float* key_  = (const float*)d_in[1];
    const float* value = (const float*)d_in[2];
    const float* w_q   = (const float*)d_in[3];
    const float* b_q   = (const float*)d_in[4];
    const float* w_k   = (const float*)d_in[5];
    const float* b_k   = (const float*)d_in[6];
    const float* w_v   = (const float*)d_in[7];
    const float* b_v   = (const float*)d_in[8];
    const float* w_o   = (const float*)d_in[9];
    const float* b_o   = (const float*)d_in[10];
    float* out = (float*)d_out;

    cudaFuncSetAttribute(gemm_qkv_tc, cudaFuncAttributeMaxDynamicSharedMemorySize, GEMM_SMEM_BYTES);
    cudaFuncSetAttribute(gemm_out_tc, cudaFuncAttributeMaxDynamicSharedMemorySize, GEMM_SMEM_BYTES);
    cudaFuncSetAttribute(attn_mma_kernel, cudaFuncAttributeMaxDynamicSharedMemorySize, ATT_SMEM);

    const int nX4 = Mrows * Dm / 4;
    const int nW4 = Dm * Dm / 4;

    // 1) tf32 RN pre-rounding
    round_x3<<<dim3(nX4 / 256, 1, 3), 256>>>(query, key_, value);
    round_w4<<<dim3(nW4 / 256, 1, 4), 256>>>(w_q, w_k, w_v, w_o);

    // 2) QKV projections
    gemm_qkv_tc<<<dim3(8, 64, 3), 256, GEMM_SMEM_BYTES>>>(b_q, b_k, b_v);

    // 3) attention: 128-row q-tiles, 8 warps/CTA
    attn_mma_kernel<<<dim3(16, 64), 256, ATT_SMEM>>>();

    // 4) output projection -> d_out
    gemm_out_tc<<<dim3(8, 64), 256, GEMM_SMEM_BYTES>>>(b_o, out);
}

// round 8
// speedup vs baseline: 1.8121x; 1.8121x over previous
#include <cuda_runtime.h>
#include <cuda_fp16.h>
#include <cstdint>

// Problem constants
#define Bsz 4
#define Ssz 2048
#define Hn  16
#define DKk 64
#define Dm  1024
#define Mrows (Bsz*Ssz)   // 8192

// ---------------- scratch (__device__ globals, fp16) ------------------------
__device__ __align__(1024) __half g_Xq[(size_t)Mrows*Dm];
__device__ __align__(1024) __half g_Xk[(size_t)Mrows*Dm];
__device__ __align__(1024) __half g_Xv[(size_t)Mrows*Dm];
__device__ __align__(1024) __half g_Wq[(size_t)Dm*Dm];
__device__ __align__(1024) __half g_Wk[(size_t)Dm*Dm];
__device__ __align__(1024) __half g_Wv[(size_t)Dm*Dm];
__device__ __align__(1024) __half g_Wo[(size_t)Dm*Dm];
__device__ __align__(1024) __half g_Q[(size_t)Bsz*Hn*Ssz*DKk];    // [b,h,s,d], pre-scaled 1/8
__device__ __align__(1024) __half g_K[(size_t)Bsz*Hn*Ssz*DKk];    // [b,h,s,d]
__device__ __align__(1024) __half g_Vt[(size_t)Bsz*Hn*DKk*Ssz];   // [b,h,d,s]  TRANSPOSED
__device__ __align__(1024) __half g_attn[(size_t)Mrows*Dm];       // [B*S, D]

// ---------------- helpers ----------------------------------------------------
__device__ __forceinline__ uint32_t smem_u32(const void* p) {
    uint32_t a;
    asm("{ .reg .u64 t; cvta.to.shared.u64 t, %1; cvt.u32.u64 %0, t; }" : "=r"(a) : "l"(p));
    return a;
}
__device__ __forceinline__ void cp_async16(uint32_t dst, const void* src) {
    asm volatile("cp.async.cg.shared.global [%0], [%1], 16;" :: "r"(dst), "l"(src));
}
#define CP_COMMIT() asm volatile("cp.async.commit_group;" ::: "memory")
#define CP_WAIT0()  asm volatile("cp.async.wait_group 0;" ::: "memory")
#define CP_WAIT1()  asm volatile("cp.async.wait_group 1;" ::: "memory")

__device__ __forceinline__ void mma_f16(float* c, const uint32_t* a, uint32_t b0, uint32_t b1) {
    asm volatile(
        "mma.sync.aligned.m16n8k16.row.col.f32.f16.f16.f32 "
        "{%0,%1,%2,%3}, {%4,%5,%6,%7}, {%8,%9}, {%0,%1,%2,%3};"
        : "+f"(c[0]), "+f"(c[1]), "+f"(c[2]), "+f"(c[3])
        : "r"(a[0]), "r"(a[1]), "r"(a[2]), "r"(a[3]), "r"(b0), "r"(b1));
}
__device__ __forceinline__ uint32_t ldu32(const __half* p) { return *(const uint32_t*)p; }

// ---------------------------------------------------------------------------
// fp16 NT GEMM: C[m,n] = sum_k X[m,k]*W[n,k] + bias[n]
// CTA 128x128x32, 8 warps (2x4), warp 64x32, 3-stage cp.async.
// modes: 0 = f32 out [M,Dm]; 1 = Q half [b,h,s,d] (scaled 1/8);
//        2 = K half [b,h,s,d]; 3 = V half transposed [b,h,d,s]
// ---------------------------------------------------------------------------
#define LDH 40
#define GEMM_SMEM_BYTES (6 * 128 * LDH * 2)   // 61440 B

__device__ __forceinline__ void gemm_f16_body(const __half* __restrict__ X,
                                              const __half* __restrict__ W,
                                              const float* __restrict__ bias,
                                              void* __restrict__ outp,
                                              int mode)
{
    extern __shared__ __half smh[];
    __half* Abuf[3] = { smh,               smh + 128*LDH,     smh + 2*128*LDH };
    __half* Bbuf[3] = { smh + 3*128*LDH,   smh + 4*128*LDH,   smh + 5*128*LDH };

    const int tid  = threadIdx.x;
    const int lane = tid & 31, wid = tid >> 5;
    const int wm   = wid >> 2, wn = wid & 3;
    const int g    = lane >> 2, q = lane & 3;
    const int bm   = blockIdx.y * 128;
    const int bn   = blockIdx.x * 128;

    float acc[4][4][4];
#pragma unroll
    for (int i = 0; i < 4; i++)
#pragma unroll
        for (int j = 0; j < 4; j++)
#pragma unroll
            for (int k = 0; k < 4; k++) acc[i][j][k] = 0.f;

    auto issue_tile = [&](int kt, int buf) {
#pragma unroll
        for (int i = 0; i < 2; i++) {            // A: 128 rows x 4 chunks
            int idx = i * 256 + tid;
            int r = idx >> 2, c = idx & 3;
            cp_async16(smem_u32(&Abuf[buf][r * LDH + c * 8]),
                       X + (size_t)(bm + r) * Dm + kt * 32 + c * 8);
        }
#pragma unroll
        for (int i = 0; i < 2; i++) {            // B
            int idx = i * 256 + tid;
            int r = idx >> 2, c = idx & 3;
            cp_async16(smem_u32(&Bbuf[buf][r * LDH + c * 8]),
                       W + (size_t)(bn + r) * Dm + kt * 32 + c * 8);
        }
        CP_COMMIT();
    };

    const int NT = Dm / 32;
    issue_tile(0, 0);
    issue_tile(1, 1);

    int buf = 0;
    for (int kt = 0; kt < NT; kt++) {
        if (kt + 1 < NT) { CP_WAIT1(); } else { CP_WAIT0(); }
        __syncthreads();
        if (kt + 2 < NT) {
            int nb = buf + 2; if (nb >= 3) nb -= 3;
            issue_tile(kt + 2, nb);
        }

        const __half* Ab = Abuf[buf];
        const __half* Bb = Bbuf[buf];
#pragma unroll
        for (int kk = 0; kk < 2; kk++) {         // two k16 slices per 32-chunk
            uint32_t afr[4][4], bfr[4][2];
#pragma unroll
            for (int mt = 0; mt < 4; mt++) {
                const __half* pa = Ab + (wm*64 + mt*16 + g) * LDH + kk*16 + 2*q;
                afr[mt][0] = ldu32(pa);
                afr[mt][1] = ldu32(pa + 8 * LDH);
                afr[mt][2] = ldu32(pa + 8);
                afr[mt][3] = ldu32(pa + 8 * LDH + 8);
            }
#pragma unroll
            for (int nt = 0; nt < 4; nt++) {
                const __half* pb = Bb + (wn*32 + nt*8 + g) * LDH + kk*16 + 2*q;
                bfr[nt][0] = ldu32(pb);
                bfr[nt][1] = ldu32(pb + 8);
            }
#pragma unroll
            for (int mt = 0; mt < 4; mt++)
#pragma unroll
                for (int nt = 0; nt < 4; nt++)
                    mma_f16(acc[mt][nt], afr[mt], bfr[nt][0], bfr[nt][1]);
        }
        __syncthreads();
        buf = buf + 1; if (buf >= 3) buf = 0;
    }

    // epilogue: c0=(r0,n) c1=(r0,n+1) c2=(r0+8,n) c3=(r0+8,n+1)
#pragma unroll
    for (int mt = 0; mt < 4; mt++) {
        int r0 = bm + wm * 64 + mt * 16 + g;
        int r1 = r0 + 8;
#pragma unroll
        for (int nt = 0; nt < 4; nt++) {
            int n = bn + wn * 32 + nt * 8 + q * 2;
            float bn0 = bias[n], bn1 = bias[n + 1];
            float c0 = acc[mt][nt][0] + bn0, c1 = acc[mt][nt][1] + bn1;
            float c2 = acc[mt][nt][2] + bn0, c3 = acc[mt][nt][3] + bn1;
            if (mode == 0) {
                float* fo = (float*)outp;
                *(float2*)&fo[(size_t)r0 * Dm + n] = make_float2(c0, c1);
                *(float2*)&fo[(size_t)r1 * Dm + n] = make_float2(c2, c3);
            } else if (mode == 3) {               // V transposed [b,h,d,s]
                int h = n >> 6, d = n & 63;
                int b0i = r0 >> 11, s0 = r0 & (Ssz - 1);
                int b1i = r1 >> 11, s1 = r1 & (Ssz - 1);
                __half* vo = (__half*)outp;
                vo[((size_t)((b0i*Hn + h)*DKk + d    ))*Ssz + s0] = __float2half_rn(c0);
                vo[((size_t)((b0i*Hn + h)*DKk + d + 1))*Ssz + s0] = __float2half_rn(c1);
                vo[((size_t)((b1i*Hn + h)*DKk + d    ))*Ssz + s1] = __float2half_rn(c2);
                vo[((size_t)((b1i*Hn + h)*DKk + d + 1))*Ssz + s1] = __float2half_rn(c3);
            } else {                              // Q (scaled) or K, [b,h,s,d]
                float sc = (mode == 1) ? 0.125f : 1.0f;
                int h = n >> 6, d = n & 63;
                int b0i = r0 >> 11, s0 = r0 & (Ssz - 1);
                int b1i = r1 >> 11, s1 = r1 & (Ssz - 1);
                __half* ho = (__half*)outp;
                *(__half2*)&ho[((size_t)((b0i*Hn + h)*Ssz + s0))*DKk + d] =
                    __floats2half2_rn(c0 * sc, c1 * sc);
                *(__half2*)&ho[((size_t)((b1i*Hn + h)*Ssz + s1))*DKk + d] =
                    __floats2half2_rn(c2 * sc, c3 * sc);
            }
        }
    }
}

__global__ __launch_bounds__(256, 2) void gemm_qkv_f16(const float* __restrict__ bq,
                                                       const float* __restrict__ bk,
                                                       const float* __restrict__ bv)
{
    if (blockIdx.z == 0)      gemm_f16_body(g_Xq, g_Wq, bq, g_Q,  1);
    else if (blockIdx.z == 1) gemm_f16_body(g_Xk, g_Wk, bk, g_K,  2);
    else                      gemm_f16_body(g_Xv, g_Wv, bv, g_Vt, 3);
}

__global__ __launch_bounds__(256, 2) void gemm_out_f16(const float* __restrict__ bo,
                                                       float* __restrict__ out)
{
    gemm_f16_body(g_attn, g_Wo, bo, out, 0);
}

// ---------------------------------------------------------------------------
// f32 -> fp16 RN conversion of GEMM inputs
// ---------------------------------------------------------------------------
__global__ __launch_bounds__(256) void conv_x3(const float* __restrict__ xq,
                                               const float* __restrict__ xk,
                                               const float* __restrict__ xv)
{
    const float* s; __half* d;
    if (blockIdx.z == 0)      { s = xq; d = g_Xq; }
    else if (blockIdx.z == 1) { s = xk; d = g_Xk; }
    else                      { s = xv; d = g_Xv; }
    int i = blockIdx.x * blockDim.x + threadIdx.x;
    float4 v = ((const float4*)s)[i];
    __half2 h0 = __floats2half2_rn(v.x, v.y);
    __half2 h1 = __floats2half2_rn(v.z, v.w);
    uint2 o = { *(uint32_t*)&h0, *(uint32_t*)&h1 };
    *(uint2*)&d[(size_t)i * 4] = o;
}

__global__ __launch_bounds__(256) void conv_w4(const float* __restrict__ wq,
                                               const float* __restrict__ wk,
                                               const float* __restrict__ wv,
                                               const float* __restrict__ wo)
{
    const float* s; __half* d;
    if (blockIdx.z == 0)      { s = wq; d = g_Wq; }
    else if (blockIdx.z == 1) { s = wk; d = g_Wk; }
    else if (blockIdx.z == 2) { s = wv; d = g_Wv; }
    else                      { s = wo; d = g_Wo; }
    int i = blockIdx.x * blockDim.x + threadIdx.x;
    float4 v = ((const float4*)s)[i];
    __half2 h0 = __floats2half2_rn(v.x, v.y);
    __half2 h1 = __floats2half2_rn(v.z, v.w);
    uint2 o = { *(uint32_t*)&h0, *(uint32_t*)&h1 };
    *(uint2*)&d[(size_t)i * 4] = o;
}

// ---------------------------------------------------------------------------
// Flash attention, fp16 mma (f32 accum/softmax).
// CTA = 128 q-rows x bh, 8 warps, warp owns 16 rows.
// K tile [key][d] and V tile [d][key] (from g_Vt) both row=128B fp16,
// double-buffered cp.async. All fragment LDS are conflict-free half2.
// ---------------------------------------------------------------------------
#define LDKH 72
#define KTILE_H (64 * LDKH)
#define ATT_SMEM ((4 * KTILE_H + 128 * LDKH) * 2)   // 55296 B

__global__ __launch_bounds__(256, 2) void attn_f16_kernel()
{
    extern __shared__ __half smh[];
    __half* Kbuf[2] = { smh,               smh + KTILE_H };
    __half* Vbuf[2] = { smh + 2*KTILE_H,   smh + 3*KTILE_H };
    __half* Ps      =   smh + 4*KTILE_H;   // [128][LDKH] (Q stage, then P)

    const int bh = blockIdx.y;
    const int qb = blockIdx.x * 128;
    const int tid = threadIdx.x;
    const int lane = tid & 31, w = tid >> 5;
    const int g = lane >> 2, q = lane & 3;

    const __half* Qb  = g_Q  + (size_t)bh * Ssz * DKk;
    const __half* Kbp = g_K  + (size_t)bh * Ssz * DKk;
    const __half* Vtp = g_Vt + (size_t)bh * DKk * Ssz;

    // ---- stage Q tile (pre-scaled fp16) into Ps, grab fragments ----------
#pragma unroll
    for (int i = 0; i < 4; i++) {
        int idx = i * 256 + tid;
        int r = idx >> 3, c = idx & 7;
        cp_async16(smem_u32(&Ps[r * LDKH + c * 8]),
                   Qb + (size_t)(qb + r) * DKk + c * 8);
    }
    CP_COMMIT();
    CP_WAIT0();
    __syncthreads();

    uint32_t qfr[4][4];
#pragma unroll
    for (int kk = 0; kk < 4; kk++) {
        const __half* pa = &Ps[(w*16 + g) * LDKH + kk*16 + 2*q];
        qfr[kk][0] = ldu32(pa);
        qfr[kk][1] = ldu32(pa + 8 * LDKH);
        qfr[kk][2] = ldu32(pa + 8);
        qfr[kk][3] = ldu32(pa + 8 * LDKH + 8);
    }
    __syncthreads();   // Ps free for P reuse

    auto issue_kv = [&](int kt, int bufi) {
        const int base = kt * 64;
        __half* kd = Kbuf[bufi];
        __half* vd = Vbuf[bufi];
#pragma unroll
        for (int i = 0; i < 2; i++) {
            int idx = i * 256 + tid;
            int r = idx >> 3, c = idx & 7;
            cp_async16(smem_u32(&kd[r * LDKH + c * 8]),
                       Kbp + (size_t)(base + r) * DKk + c * 8);
            cp_async16(smem_u32(&vd[r * LDKH + c * 8]),
                       Vtp + (size_t)r * Ssz + base + c * 8);
        }
        CP_COMMIT();
    };

    float oacc[8][4];
#pragma unroll
    for (int nt = 0; nt < 8; nt++)
#pragma unroll
        for (int k = 0; k < 4; k++) oacc[nt][k] = 0.f;
    float mA = -1e30f, mB = -1e30f, lA = 0.f, lB = 0.f;

    const int NT = Ssz / 64;
    issue_kv(0, 0);

    for (int kt = 0; kt < NT; kt++) {
        const int buf = kt & 1;
        if (kt + 1 < NT) {
            issue_kv(kt + 1, buf ^ 1);
            CP_WAIT1();
        } else {
            CP_WAIT0();
        }
        __syncthreads();

        const __half* Ks = Kbuf[buf];
        const __half* Vs = Vbuf[buf];

        // ---- S = Q K^T : 16 x 64, 32 MMAs ----
        float sacc[8][4];
#pragma unroll
        for (int nt = 0; nt < 8; nt++)
#pragma unroll
            for (int k = 0; k < 4; k++) sacc[nt][k] = 0.f;
#pragma unroll
        for (int nt = 0; nt < 8; nt++) {
#pragma unroll
            for (int kk = 0; kk < 4; kk++) {
                const __half* pb = &Ks[(nt*8 + g) * LDKH + kk*16 + 2*q];
                mma_f16(sacc[nt], qfr[kk], ldu32(pb), ldu32(pb + 8));
            }
        }

        // ---- online softmax (rows g, g+8) ----
        float mtA = -1e30f, mtB = -1e30f;
#pragma unroll
        for (int nt = 0; nt < 8; nt++) {
            mtA = fmaxf(mtA, fmaxf(sacc[nt][0], sacc[nt][1]));
            mtB = fmaxf(mtB, fmaxf(sacc[nt][2], sacc[nt][3]));
        }
        mtA = fmaxf(mtA, __shfl_xor_sync(0xffffffffu, mtA, 1));
        mtA = fmaxf(mtA, __shfl_xor_sync(0xffffffffu, mtA, 2));
        mtB = fmaxf(mtB, __shfl_xor_sync(0xffffffffu, mtB, 1));
        mtB = fmaxf(mtB, __shfl_xor_sync(0xffffffffu, mtB, 2));

        float mnA = fmaxf(mA, mtA), mnB = fmaxf(mB, mtB);
        float corrA = __expf(mA - mnA), corrB = __expf(mB - mnB);
        mA = mnA; mB = mnB;

        float sA = 0.f, sB = 0.f;
        __half* prowA = &Ps[(w*16 + g) * LDKH];
        __half* prowB = &Ps[(w*16 + g + 8) * LDKH];
#pragma unroll
        for (int nt = 0; nt < 8; nt++) {
            float p0 = __expf(sacc[nt][0] - mA);
            float p1 = __expf(sacc[nt][1] - mA);
            float p2 = __expf(sacc[nt][2] - mB);
            float p3 = __expf(sacc[nt][3] - mB);
            sA += p0 + p1;
            sB += p2 + p3;
            *(__half2*)&prowA[nt*8 + 2*q] = __floats2half2_rn(p0, p1);
            *(__half2*)&prowB[nt*8 + 2*q] = __floats2half2_rn(p2, p3);
        }
        sA += __shfl_xor_sync(0xffffffffu, sA, 1);
        sA += __shfl_xor_sync(0xffffffffu, sA, 2);
        sB += __shfl_xor_sync(0xffffffffu, sB, 1);
        sB += __shfl_xor_sync(0xffffffffu, sB, 2);
        lA = lA * corrA + sA;
        lB = lB * corrB + sB;

#pragma unroll
        for (int nt = 0; nt < 8; nt++) {
            oacc[nt][0] *= corrA; oacc[nt][1] *= corrA;
            oacc[nt][2] *= corrB; oacc[nt][3] *= corrB;
        }
        __syncwarp();

        // ---- O += P * V : B-frags contiguous half2 from Vt rows ----
#pragma unroll
        for (int kk = 0; kk < 4; kk++) {
            uint32_t afr[4];
            const __half* pa = &Ps[(w*16 + g) * LDKH + kk*16 + 2*q];
            afr[0] = ldu32(pa);
            afr[1] = ldu32(pa + 8 * LDKH);
            afr[2] = ldu32(pa + 8);
            afr[3] = ldu32(pa + 8 * LDKH + 8);
#pragma unroll
            for (int nt = 0; nt < 8; nt++) {
                const __half* pb = &Vs[(nt*8 + g) * LDKH + kk*16 + 2*q];
                mma_f16(oacc[nt], afr, ldu32(pb), ldu32(pb + 8));
            }
        }
        __syncthreads();
    }

    // ---- epilogue: normalize, fp16 RN, write g_attn -----------------------
    float invA = 1.f / lA, invB = 1.f / lB;
    int b = bh >> 4, h = bh & 15;
    int row0 = qb + w * 16 + g;
    int row1 = row0 + 8;
#pragma unroll
    for (int nt = 0; nt < 8; nt++) {
        int col = h * DKk + nt * 8 + q * 2;
        *(__half2*)&g_attn[(size_t)(b * Ssz + row0) * Dm + col] =
            __floats2half2_rn(oacc[nt][0] * invA, oacc[nt][1] * invA);
        *(__half2*)&g_attn[(size_t)(b * Ssz + row1) * Dm + col] =
            __floats2half2_rn(oacc[nt][2] * invB, oacc[nt][3] * invB);
    }
}

// ---------------------------------------------------------------------------
extern "C" void kernel_launch(void* const* d_in, const int* in_sizes, int n_in,
                              void* d_out, int out_size)
{
    const float* query = (const float*)d_in[0];
    const float* key_  = (const float*)d_in[1];
    const float* value = (const float*)d_in[2];
    const float* w_q   = (const float*)d_in[3];
    const float* b_q   = (const float*)d_in[4];
    const float* w_k   = (const float*)d_in[5];
    const float* b_k   = (const float*)d_in[6];
    const float* w_v   = (const float*)d_in[7];
    const float* b_v   = (const float*)d_in[8];
    const float* w_o   = (const float*)d_in[9];
    const float* b_o   = (const float*)d_in[10];
    float* out = (float*)d_out;

    cudaFuncSetAttribute(gemm_qkv_f16, cudaFuncAttributeMaxDynamicSharedMemorySize, GEMM_SMEM_BYTES);
    cudaFuncSetAttribute(gemm_out_f16, cudaFuncAttributeMaxDynamicSharedMemorySize, GEMM_SMEM_BYTES);
    cudaFuncSetAttribute(attn_f16_kernel, cudaFuncAttributeMaxDynamicSharedMemorySize, ATT_SMEM);

    const int nX4 = Mrows * Dm / 4;   // 2,097,152
    const int nW4 = Dm * Dm / 4;      //   262,144

    // 1) f32 -> fp16 RN conversion of GEMM inputs
    conv_x3<<<dim3(nX4 / 256, 1, 3), 256>>>(query, key_, value);
    conv_w4<<<dim3(nW4 / 256, 1, 4), 256>>>(w_q, w_k, w_v, w_o);

    // 2) QKV projections (fp16 mma) -> g_Q (scaled), g_K, g_Vt (transposed)
    gemm_qkv_f16<<<dim3(8, 64, 3), 256, GEMM_SMEM_BYTES>>>(b_q, b_k, b_v);

    // 3) attention (fp16 mma flash), 128-row q-tiles
    attn_f16_kernel<<<dim3(16, 64), 256, ATT_SMEM>>>();

    // 4) output projection (fp16 mma) -> d_out (f32)
    gemm_out_f16<<<dim3(8, 64), 256, GEMM_SMEM_BYTES>>>(b_o, out);
}

// round 9
// speedup vs baseline: 1.8981x; 1.0475x over previous
#include <cuda_runtime.h>
#include <cuda_fp16.h>
#include <cstdint>

// Problem constants
#define Bsz 4
#define Ssz 2048
#define Hn  16
#define DKk 64
#define Dm  1024
#define Mrows (Bsz*Ssz)   // 8192

// ---------------- scratch (__device__ globals, fp16) ------------------------
__device__ __align__(1024) __half g_Xq[(size_t)Mrows*Dm];
__device__ __align__(1024) __half g_Xk[(size_t)Mrows*Dm];
__device__ __align__(1024) __half g_Xv[(size_t)Mrows*Dm];
__device__ __align__(1024) __half g_Wq[(size_t)Dm*Dm];
__device__ __align__(1024) __half g_Wk[(size_t)Dm*Dm];
__device__ __align__(1024) __half g_Wv[(size_t)Dm*Dm];
__device__ __align__(1024) __half g_Wo[(size_t)Dm*Dm];
__device__ __align__(1024) __half g_Q[(size_t)Bsz*Hn*Ssz*DKk];    // [b,h,s,d], pre-scaled log2e/8
__device__ __align__(1024) __half g_K[(size_t)Bsz*Hn*Ssz*DKk];    // [b,h,s,d]
__device__ __align__(1024) __half g_Vt[(size_t)Bsz*Hn*DKk*Ssz];   // [b,h,d,s]  TRANSPOSED
__device__ __align__(1024) __half g_attn[(size_t)Mrows*Dm];       // [B*S, D]

// ---------------- helpers ----------------------------------------------------
__device__ __forceinline__ uint32_t smem_u32(const void* p) {
    uint32_t a;
    asm("{ .reg .u64 t; cvta.to.shared.u64 t, %1; cvt.u32.u64 %0, t; }" : "=r"(a) : "l"(p));
    return a;
}
__device__ __forceinline__ void cp_async16(uint32_t dst, const void* src) {
    asm volatile("cp.async.cg.shared.global [%0], [%1], 16;" :: "r"(dst), "l"(src));
}
#define CP_COMMIT() asm volatile("cp.async.commit_group;" ::: "memory")
#define CP_WAIT0()  asm volatile("cp.async.wait_group 0;" ::: "memory")
#define CP_WAIT1()  asm volatile("cp.async.wait_group 1;" ::: "memory")

__device__ __forceinline__ void mma_f16(float* c, const uint32_t* a, uint32_t b0, uint32_t b1) {
    asm volatile(
        "mma.sync.aligned.m16n8k16.row.col.f32.f16.f16.f32 "
        "{%0,%1,%2,%3}, {%4,%5,%6,%7}, {%8,%9}, {%0,%1,%2,%3};"
        : "+f"(c[0]), "+f"(c[1]), "+f"(c[2]), "+f"(c[3])
        : "r"(a[0]), "r"(a[1]), "r"(a[2]), "r"(a[3]), "r"(b0), "r"(b1));
}
__device__ __forceinline__ uint32_t ldu32(const __half* p) { return *(const uint32_t*)p; }
__device__ __forceinline__ uint32_t packh2(float a, float b) {
    __half2 h = __floats2half2_rn(a, b);
    return *(uint32_t*)&h;
}

// ---------------------------------------------------------------------------
// fp16 NT GEMM (unchanged from R8). modes: 0 f32 [M,Dm]; 1 Q (scaled log2e/8);
// 2 K; 3 V transposed [b,h,d,s]
// ---------------------------------------------------------------------------
#define LDH 40
#define GEMM_SMEM_BYTES (6 * 128 * LDH * 2)   // 61440 B

__device__ __forceinline__ void gemm_f16_body(const __half* __restrict__ X,
                                              const __half* __restrict__ W,
                                              const float* __restrict__ bias,
                                              void* __restrict__ outp,
                                              int mode)
{
    extern __shared__ __half smh[];
    __half* Abuf[3] = { smh,               smh + 128*LDH,     smh + 2*128*LDH };
    __half* Bbuf[3] = { smh + 3*128*LDH,   smh + 4*128*LDH,   smh + 5*128*LDH };

    const int tid  = threadIdx.x;
    const int lane = tid & 31, wid = tid >> 5;
    const int wm   = wid >> 2, wn = wid & 3;
    const int g    = lane >> 2, q = lane & 3;
    const int bm   = blockIdx.y * 128;
    const int bn   = blockIdx.x * 128;

    float acc[4][4][4];
#pragma unroll
    for (int i = 0; i < 4; i++)
#pragma unroll
        for (int j = 0; j < 4; j++)
#pragma unroll
            for (int k = 0; k < 4; k++) acc[i][j][k] = 0.f;

    auto issue_tile = [&](int kt, int buf) {
#pragma unroll
        for (int i = 0; i < 2; i++) {
            int idx = i * 256 + tid;
            int r = idx >> 2, c = idx & 3;
            cp_async16(smem_u32(&Abuf[buf][r * LDH + c * 8]),
                       X + (size_t)(bm + r) * Dm + kt * 32 + c * 8);
        }
#pragma unroll
        for (int i = 0; i < 2; i++) {
            int idx = i * 256 + tid;
            int r = idx >> 2, c = idx & 3;
            cp_async16(smem_u32(&Bbuf[buf][r * LDH + c * 8]),
                       W + (size_t)(bn + r) * Dm + kt * 32 + c * 8);
        }
        CP_COMMIT();
    };

    const int NT = Dm / 32;
    issue_tile(0, 0);
    issue_tile(1, 1);

    int buf = 0;
    for (int kt = 0; kt < NT; kt++) {
        if (kt + 1 < NT) { CP_WAIT1(); } else { CP_WAIT0(); }
        __syncthreads();
        if (kt + 2 < NT) {
            int nb = buf + 2; if (nb >= 3) nb -= 3;
            issue_tile(kt + 2, nb);
        }

        const __half* Ab = Abuf[buf];
        const __half* Bb = Bbuf[buf];
#pragma unroll
        for (int kk = 0; kk < 2; kk++) {
            uint32_t afr[4][4], bfr[4][2];
#pragma unroll
            for (int mt = 0; mt < 4; mt++) {
                const __half* pa = Ab + (wm*64 + mt*16 + g) * LDH + kk*16 + 2*q;
                afr[mt][0] = ldu32(pa);
                afr[mt][1] = ldu32(pa + 8 * LDH);
                afr[mt][2] = ldu32(pa + 8);
                afr[mt][3] = ldu32(pa + 8 * LDH + 8);
            }
#pragma unroll
            for (int nt = 0; nt < 4; nt++) {
                const __half* pb = Bb + (wn*32 + nt*8 + g) * LDH + kk*16 + 2*q;
                bfr[nt][0] = ldu32(pb);
                bfr[nt][1] = ldu32(pb + 8);
            }
#pragma unroll
            for (int mt = 0; mt < 4; mt++)
#pragma unroll
                for (int nt = 0; nt < 4; nt++)
                    mma_f16(acc[mt][nt], afr[mt], bfr[nt][0], bfr[nt][1]);
        }
        __syncthreads();
        buf = buf + 1; if (buf >= 3) buf = 0;
    }

#pragma unroll
    for (int mt = 0; mt < 4; mt++) {
        int r0 = bm + wm * 64 + mt * 16 + g;
        int r1 = r0 + 8;
#pragma unroll
        for (int nt = 0; nt < 4; nt++) {
            int n = bn + wn * 32 + nt * 8 + q * 2;
            float bn0 = bias[n], bn1 = bias[n + 1];
            float c0 = acc[mt][nt][0] + bn0, c1 = acc[mt][nt][1] + bn1;
            float c2 = acc[mt][nt][2] + bn0, c3 = acc[mt][nt][3] + bn1;
            if (mode == 0) {
                float* fo = (float*)outp;
                *(float2*)&fo[(size_t)r0 * Dm + n] = make_float2(c0, c1);
                *(float2*)&fo[(size_t)r1 * Dm + n] = make_float2(c2, c3);
            } else if (mode == 3) {
                int h = n >> 6, d = n & 63;
                int b0i = r0 >> 11, s0 = r0 & (Ssz - 1);
                int b1i = r1 >> 11, s1 = r1 & (Ssz - 1);
                __half* vo = (__half*)outp;
                vo[((size_t)((b0i*Hn + h)*DKk + d    ))*Ssz + s0] = __float2half_rn(c0);
                vo[((size_t)((b0i*Hn + h)*DKk + d + 1))*Ssz + s0] = __float2half_rn(c1);
                vo[((size_t)((b1i*Hn + h)*DKk + d    ))*Ssz + s1] = __float2half_rn(c2);
                vo[((size_t)((b1i*Hn + h)*DKk + d + 1))*Ssz + s1] = __float2half_rn(c3);
            } else {
                // Q: fold softmax scale AND log2(e) so attention uses exp2
                float sc = (mode == 1) ? (0.125f * 1.4426950408889634f) : 1.0f;
                int h = n >> 6, d = n & 63;
                int b0i = r0 >> 11, s0 = r0 & (Ssz - 1);
                int b1i = r1 >> 11, s1 = r1 & (Ssz - 1);
                __half* ho = (__half*)outp;
                *(__half2*)&ho[((size_t)((b0i*Hn + h)*Ssz + s0))*DKk + d] =
                    __floats2half2_rn(c0 * sc, c1 * sc);
                *(__half2*)&ho[((size_t)((b1i*Hn + h)*Ssz + s1))*DKk + d] =
                    __floats2half2_rn(c2 * sc, c3 * sc);
            }
        }
    }
}

__global__ __launch_bounds__(256, 2) void gemm_qkv_f16(const float* __restrict__ bq,
                                                       const float* __restrict__ bk,
                                                       const float* __restrict__ bv)
{
    if (blockIdx.z == 0)      gemm_f16_body(g_Xq, g_Wq, bq, g_Q,  1);
    else if (blockIdx.z == 1) gemm_f16_body(g_Xk, g_Wk, bk, g_K,  2);
    else                      gemm_f16_body(g_Xv, g_Wv, bv, g_Vt, 3);
}

__global__ __launch_bounds__(256, 2) void gemm_out_f16(const float* __restrict__ bo,
                                                       float* __restrict__ out)
{
    gemm_f16_body(g_attn, g_Wo, bo, out, 0);
}

// ---------------------------------------------------------------------------
// f32 -> fp16 RN conversion of GEMM inputs
// ---------------------------------------------------------------------------
__global__ __launch_bounds__(256) void conv_x3(const float* __restrict__ xq,
                                               const float* __restrict__ xk,
                                               const float* __restrict__ xv)
{
    const float* s; __half* d;
    if (blockIdx.z == 0)      { s = xq; d = g_Xq; }
    else if (blockIdx.z == 1) { s = xk; d = g_Xk; }
    else                      { s = xv; d = g_Xv; }
    int i = blockIdx.x * blockDim.x + threadIdx.x;
    float4 v = ((const float4*)s)[i];
    __half2 h0 = __floats2half2_rn(v.x, v.y);
    __half2 h1 = __floats2half2_rn(v.z, v.w);
    uint2 o = { *(uint32_t*)&h0, *(uint32_t*)&h1 };
    *(uint2*)&d[(size_t)i * 4] = o;
}

__global__ __launch_bounds__(256) void conv_w4(const float* __restrict__ wq,
                                               const float* __restrict__ wk,
                                               const float* __restrict__ wv,
                                               const float* __restrict__ wo)
{
    const float* s; __half* d;
    if (blockIdx.z == 0)      { s = wq; d = g_Wq; }
    else if (blockIdx.z == 1) { s = wk; d = g_Wk; }
    else if (blockIdx.z == 2) { s = wv; d = g_Wv; }
    else                      { s = wo; d = g_Wo; }
    int i = blockIdx.x * blockDim.x + threadIdx.x;
    float4 v = ((const float4*)s)[i];
    __half2 h0 = __floats2half2_rn(v.x, v.y);
    __half2 h1 = __floats2half2_rn(v.z, v.w);
    uint2 o = { *(uint32_t*)&h0, *(uint32_t*)&h1 };
    *(uint2*)&d[(size_t)i * 4] = o;
}

// ---------------------------------------------------------------------------
// Flash attention, fp16 mma, REGISTER-RESIDENT P.
// The S-accumulator fragment layout (m16n8k16 D) equals the PV A-fragment
// layout: afr[kk] = { pA[2kk], pB[2kk], pA[2kk+1], pB[2kk+1] } where
// pA[nt]=h2(p(g,nt8+2q),p(+1)), pB[nt]=same for row g+8. No P smem, no
// round-trip. Softmax in exp2 domain (log2e folded into Q).
// ---------------------------------------------------------------------------
#define LDKH 72
#define KTILE_H (64 * LDKH)
#define ATT_SMEM (4 * KTILE_H * 2)   // K x2, V x2 = 36864 B

__global__ __launch_bounds__(256, 2) void attn_f16_kernel()
{
    extern __shared__ __half smh[];
    __half* Kbuf[2] = { smh,               smh + KTILE_H };
    __half* Vbuf[2] = { smh + 2*KTILE_H,   smh + 3*KTILE_H };

    const int bh = blockIdx.y;
    const int qb = blockIdx.x * 128;
    const int tid = threadIdx.x;
    const int lane = tid & 31, w = tid >> 5;
    const int g = lane >> 2, q = lane & 3;

    const __half* Qb  = g_Q  + (size_t)bh * Ssz * DKk;
    const __half* Kbp = g_K  + (size_t)bh * Ssz * DKk;
    const __half* Vtp = g_Vt + (size_t)bh * DKk * Ssz;

    // ---- stage Q tile (128 rows) into K/V smem area, grab fragments -------
#pragma unroll
    for (int i = 0; i < 4; i++) {
        int idx = i * 256 + tid;
        int r = idx >> 3, c = idx & 7;
        cp_async16(smem_u32(&smh[r * LDKH + c * 8]),
                   Qb + (size_t)(qb + r) * DKk + c * 8);
    }
    CP_COMMIT();
    CP_WAIT0();
    __syncthreads();

    uint32_t qfr[4][4];
#pragma unroll
    for (int kk = 0; kk < 4; kk++) {
        const __half* pa = &smh[(w*16 + g) * LDKH + kk*16 + 2*q];
        qfr[kk][0] = ldu32(pa);
        qfr[kk][1] = ldu32(pa + 8 * LDKH);
        qfr[kk][2] = ldu32(pa + 8);
        qfr[kk][3] = ldu32(pa + 8 * LDKH + 8);
    }
    __syncthreads();   // smem free for K/V pipeline

    auto issue_kv = [&](int kt, int bufi) {
        const int base = kt * 64;
        __half* kd = Kbuf[bufi];
        __half* vd = Vbuf[bufi];
#pragma unroll
        for (int i = 0; i < 2; i++) {
            int idx = i * 256 + tid;
            int r = idx >> 3, c = idx & 7;
            cp_async16(smem_u32(&kd[r * LDKH + c * 8]),
                       Kbp + (size_t)(base + r) * DKk + c * 8);
            cp_async16(smem_u32(&vd[r * LDKH + c * 8]),
                       Vtp + (size_t)r * Ssz + base + c * 8);
        }
        CP_COMMIT();
    };

    float oacc[8][4];
#pragma unroll
    for (int nt = 0; nt < 8; nt++)
#pragma unroll
        for (int k = 0; k < 4; k++) oacc[nt][k] = 0.f;
    float mA = -1e30f, mB = -1e30f, lA = 0.f, lB = 0.f;

    const int NT = Ssz / 64;
    issue_kv(0, 0);

    for (int kt = 0; kt < NT; kt++) {
        const int buf = kt & 1;
        if (kt + 1 < NT) {
            issue_kv(kt + 1, buf ^ 1);
            CP_WAIT1();
        } else {
            CP_WAIT0();
        }
        __syncthreads();

        const __half* Ks = Kbuf[buf];
        const __half* Vs = Vbuf[buf];

        // ---- S = Q K^T (scores already in log2 domain) ----
        float sacc[8][4];
#pragma unroll
        for (int nt = 0; nt < 8; nt++)
#pragma unroll
            for (int k = 0; k < 4; k++) sacc[nt][k] = 0.f;
#pragma unroll
        for (int nt = 0; nt < 8; nt++) {
#pragma unroll
            for (int kk = 0; kk < 4; kk++) {
                const __half* pb = &Ks[(nt*8 + g) * LDKH + kk*16 + 2*q];
                mma_f16(sacc[nt], qfr[kk], ldu32(pb), ldu32(pb + 8));
            }
        }

        // ---- online softmax (base 2), P packed to registers ----
        float mtA = -1e30f, mtB = -1e30f;
#pragma unroll
        for (int nt = 0; nt < 8; nt++) {
            mtA = fmaxf(mtA, fmaxf(sacc[nt][0], sacc[nt][1]));
            mtB = fmaxf(mtB, fmaxf(sacc[nt][2], sacc[nt][3]));
        }
        mtA = fmaxf(mtA, __shfl_xor_sync(0xffffffffu, mtA, 1));
        mtA = fmaxf(mtA, __shfl_xor_sync(0xffffffffu, mtA, 2));
        mtB = fmaxf(mtB, __shfl_xor_sync(0xffffffffu, mtB, 1));
        mtB = fmaxf(mtB, __shfl_xor_sync(0xffffffffu, mtB, 2));

        float mnA = fmaxf(mA, mtA), mnB = fmaxf(mB, mtB);
        float corrA = exp2f(mA - mnA), corrB = exp2f(mB - mnB);
        mA = mnA; mB = mnB;

        float sA = 0.f, sB = 0.f;
        uint32_t pA[8], pB[8];
#pragma unroll
        for (int nt = 0; nt < 8; nt++) {
            float p0 = exp2f(sacc[nt][0] - mA);
            float p1 = exp2f(sacc[nt][1] - mA);
            float p2 = exp2f(sacc[nt][2] - mB);
            float p3 = exp2f(sacc[nt][3] - mB);
            sA += p0 + p1;
            sB += p2 + p3;
            pA[nt] = packh2(p0, p1);
            pB[nt] = packh2(p2, p3);
        }
        sA += __shfl_xor_sync(0xffffffffu, sA, 1);
        sA += __shfl_xor_sync(0xffffffffu, sA, 2);
        sB += __shfl_xor_sync(0xffffffffu, sB, 1);
        sB += __shfl_xor_sync(0xffffffffu, sB, 2);
        lA = lA * corrA + sA;
        lB = lB * corrB + sB;

#pragma unroll
        for (int nt = 0; nt < 8; nt++) {
            oacc[nt][0] *= corrA; oacc[nt][1] *= corrA;
            oacc[nt][2] *= corrB; oacc[nt][3] *= corrB;
        }

        // ---- O += P * V : A-fragments straight from registers ----
#pragma unroll
        for (int kk = 0; kk < 4; kk++) {
            uint32_t afr[4] = { pA[2*kk], pB[2*kk], pA[2*kk + 1], pB[2*kk + 1] };
#pragma unroll
            for (int nt = 0; nt < 8; nt++) {
                const __half* pb = &Vs[(nt*8 + g) * LDKH + kk*16 + 2*q];
                mma_f16(oacc[nt], afr, ldu32(pb), ldu32(pb + 8));
            }
        }
        __syncthreads();
    }

    // ---- epilogue: normalize, fp16 RN, write g_attn -----------------------
    float invA = 1.f / lA, invB = 1.f / lB;
    int b = bh >> 4, h = bh & 15;
    int row0 = qb + w * 16 + g;
    int row1 = row0 + 8;
#pragma unroll
    for (int nt = 0; nt < 8; nt++) {
        int col = h * DKk + nt * 8 + q * 2;
        *(__half2*)&g_attn[(size_t)(b * Ssz + row0) * Dm + col] =
            __floats2half2_rn(oacc[nt][0] * invA, oacc[nt][1] * invA);
        *(__half2*)&g_attn[(size_t)(b * Ssz + row1) * Dm + col] =
            __floats2half2_rn(oacc[nt][2] * invB, oacc[nt][3] * invB);
    }
}

// ---------------------------------------------------------------------------
extern "C" void kernel_launch(void* const* d_in, const int* in_sizes, int n_in,
                              void* d_out, int out_size)
{
    const float* query = (const float*)d_in[0];
    const float* key_  = (const float*)d_in[1];
    const float* value = (const float*)d_in[2];
    const float* w_q   = (const float*)d_in[3];
    const float* b_q   = (const float*)d_in[4];
    const float* w_k   = (const float*)d_in[5];
    const float* b_k   = (const float*)d_in[6];
    const float* w_v   = (const float*)d_in[7];
    const float* b_v   = (const float*)d_in[8];
    const float* w_o   = (const float*)d_in[9];
    const float* b_o   = (const float*)d_in[10];
    float* out = (float*)d_out;

    cudaFuncSetAttribute(gemm_qkv_f16, cudaFuncAttributeMaxDynamicSharedMemorySize, GEMM_SMEM_BYTES);
    cudaFuncSetAttribute(gemm_out_f16, cudaFuncAttributeMaxDynamicSharedMemorySize, GEMM_SMEM_BYTES);
    cudaFuncSetAttribute(attn_f16_kernel, cudaFuncAttributeMaxDynamicSharedMemorySize, ATT_SMEM);

    const int nX4 = Mrows * Dm / 4;
    const int nW4 = Dm * Dm / 4;

    conv_x3<<<dim3(nX4 / 256, 1, 3), 256>>>(query, key_, value);
    conv_w4<<<dim3(nW4 / 256, 1, 4), 256>>>(w_q, w_k, w_v, w_o);

    gemm_qkv_f16<<<dim3(8, 64, 3), 256, GEMM_SMEM_BYTES>>>(b_q, b_k, b_v);

    attn_f16_kernel<<<dim3(16, 64), 256, ATT_SMEM>>>();

    gemm_out_f16<<<dim3(8, 64), 256, GEMM_SMEM_BYTES>>>(b_o, out);
}

// round 10
// speedup vs baseline: 2.2733x; 1.1977x over previous
#include <cuda_runtime.h>
#include <cuda_fp16.h>
#include <cstdint>

// Problem constants
#define Bsz 4
#define Ssz 2048
#define Hn  16
#define DKk 64
#define Dm  1024
#define Mrows (Bsz*Ssz)   // 8192

// ---------------- scratch (__device__ globals, fp16) ------------------------
__device__ __align__(1024) __half g_Xq[(size_t)Mrows*Dm];
__device__ __align__(1024) __half g_Xk[(size_t)Mrows*Dm];
__device__ __align__(1024) __half g_Xv[(size_t)Mrows*Dm];
__device__ __align__(1024) __half g_Wq[(size_t)Dm*Dm];
__device__ __align__(1024) __half g_Wk[(size_t)Dm*Dm];
__device__ __align__(1024) __half g_Wv[(size_t)Dm*Dm];
__device__ __align__(1024) __half g_Wo[(size_t)Dm*Dm];
__device__ __align__(1024) __half g_Q[(size_t)Bsz*Hn*Ssz*DKk];    // [b,h,s,d], pre-scaled log2e/8
__device__ __align__(1024) __half g_K[(size_t)Bsz*Hn*Ssz*DKk];    // [b,h,s,d]
__device__ __align__(1024) __half g_Vt[(size_t)Bsz*Hn*DKk*Ssz];   // [b,h,d,s]  TRANSPOSED
__device__ __align__(1024) __half g_attn[(size_t)Mrows*Dm];       // [B*S, D]

// ---------------- helpers ----------------------------------------------------
__device__ __forceinline__ uint32_t smem_u32(const void* p) {
    uint32_t a;
    asm("{ .reg .u64 t; cvta.to.shared.u64 t, %1; cvt.u32.u64 %0, t; }" : "=r"(a) : "l"(p));
    return a;
}
__device__ __forceinline__ void cp_async16(uint32_t dst, const void* src) {
    asm volatile("cp.async.cg.shared.global [%0], [%1], 16;" :: "r"(dst), "l"(src));
}
#define CP_COMMIT() asm volatile("cp.async.commit_group;" ::: "memory")
#define CP_WAIT0()  asm volatile("cp.async.wait_group 0;" ::: "memory")
#define CP_WAIT1()  asm volatile("cp.async.wait_group 1;" ::: "memory")

__device__ __forceinline__ void mma_f16(float* c, const uint32_t* a, uint32_t b0, uint32_t b1) {
    asm volatile(
        "mma.sync.aligned.m16n8k16.row.col.f32.f16.f16.f32 "
        "{%0,%1,%2,%3}, {%4,%5,%6,%7}, {%8,%9}, {%0,%1,%2,%3};"
        : "+f"(c[0]), "+f"(c[1]), "+f"(c[2]), "+f"(c[3])
        : "r"(a[0]), "r"(a[1]), "r"(a[2]), "r"(a[3]), "r"(b0), "r"(b1));
}
__device__ __forceinline__ void ldsm4(uint32_t* r, uint32_t addr) {
    asm volatile("ldmatrix.sync.aligned.m8n8.x4.shared.b16 {%0,%1,%2,%3}, [%4];"
        : "=r"(r[0]), "=r"(r[1]), "=r"(r[2]), "=r"(r[3]) : "r"(addr));
}
__device__ __forceinline__ uint32_t packh2(float a, float b) {
    __half2 h = __floats2half2_rn(a, b);
    return *(uint32_t*)&h;
}

// ---------------------------------------------------------------------------
// fp16 NT GEMM with ldmatrix fragment loads.
// CTA 128x128x32, 8 warps (2x4), warp 64x32, 3-stage cp.async.
// ---------------------------------------------------------------------------
#define LDH 40
#define GEMM_SMEM_BYTES (6 * 128 * LDH * 2)   // 61440 B

__device__ __forceinline__ void gemm_f16_body(const __half* __restrict__ X,
                                              const __half* __restrict__ W,
                                              const float* __restrict__ bias,
                                              void* __restrict__ outp,
                                              int mode)
{
    extern __shared__ __half smh[];
    __half* Abuf[3] = { smh,               smh + 128*LDH,     smh + 2*128*LDH };
    __half* Bbuf[3] = { smh + 3*128*LDH,   smh + 4*128*LDH,   smh + 5*128*LDH };

    const int tid  = threadIdx.x;
    const int lane = tid & 31, wid = tid >> 5;
    const int wm   = wid >> 2, wn = wid & 3;
    const int g    = lane >> 2, q = lane & 3;
    const int bm   = blockIdx.y * 128;
    const int bn   = blockIdx.x * 128;

    // ldmatrix per-thread address components
    const int lrow16 = lane & 15;          // A: row within 16
    const int lhi    = lane >> 4;          // A: k-half select
    const int bsub   = lane & 7;           // B: row within 8
    const int bhi8   = (lane >> 3) & 1;    // B: k-half select
    const int bnt    = lane >> 4;          // B: n-tile select within pair

    float acc[4][4][4];
#pragma unroll
    for (int i = 0; i < 4; i++)
#pragma unroll
        for (int j = 0; j < 4; j++)
#pragma unroll
            for (int k = 0; k < 4; k++) acc[i][j][k] = 0.f;

    auto issue_tile = [&](int kt, int buf) {
#pragma unroll
        for (int i = 0; i < 2; i++) {
            int idx = i * 256 + tid;
            int r = idx >> 2, c = idx & 3;
            cp_async16(smem_u32(&Abuf[buf][r * LDH + c * 8]),
                       X + (size_t)(bm + r) * Dm + kt * 32 + c * 8);
        }
#pragma unroll
        for (int i = 0; i < 2; i++) {
            int idx = i * 256 + tid;
            int r = idx >> 2, c = idx & 3;
            cp_async16(smem_u32(&Bbuf[buf][r * LDH + c * 8]),
                       W + (size_t)(bn + r) * Dm + kt * 32 + c * 8);
        }
        CP_COMMIT();
    };

    const int NT = Dm / 32;
    issue_tile(0, 0);
    issue_tile(1, 1);

    int buf = 0;
    for (int kt = 0; kt < NT; kt++) {
        if (kt + 1 < NT) { CP_WAIT1(); } else { CP_WAIT0(); }
        __syncthreads();
        if (kt + 2 < NT) {
            int nb = buf + 2; if (nb >= 3) nb -= 3;
            issue_tile(kt + 2, nb);
        }

        const __half* Ab = Abuf[buf];
        const __half* Bb = Bbuf[buf];
#pragma unroll
        for (int kk = 0; kk < 2; kk++) {
            uint32_t afr[4][4], bfr[2][4];
            const __half* pa = Ab + (wm*64 + lrow16) * LDH + kk*16 + lhi*8;
#pragma unroll
            for (int mt = 0; mt < 4; mt++)
                ldsm4(afr[mt], smem_u32(pa + mt * 16 * LDH));
            const __half* pb = Bb + (wn*32 + bnt*8 + bsub) * LDH + kk*16 + bhi8*8;
#pragma unroll
            for (int ntp = 0; ntp < 2; ntp++)
                ldsm4(bfr[ntp], smem_u32(pb + ntp * 16 * LDH));
#pragma unroll
            for (int mt = 0; mt < 4; mt++)
#pragma unroll
                for (int nt = 0; nt < 4; nt++)
                    mma_f16(acc[mt][nt], afr[mt],
                            bfr[nt >> 1][(nt & 1) * 2], bfr[nt >> 1][(nt & 1) * 2 + 1]);
        }
        __syncthreads();
        buf = buf + 1; if (buf >= 3) buf = 0;
    }

#pragma unroll
    for (int mt = 0; mt < 4; mt++) {
        int r0 = bm + wm * 64 + mt * 16 + g;
        int r1 = r0 + 8;
#pragma unroll
        for (int nt = 0; nt < 4; nt++) {
            int n = bn + wn * 32 + nt * 8 + q * 2;
            float bn0 = bias[n], bn1 = bias[n + 1];
            float c0 = acc[mt][nt][0] + bn0, c1 = acc[mt][nt][1] + bn1;
            float c2 = acc[mt][nt][2] + bn0, c3 = acc[mt][nt][3] + bn1;
            if (mode == 0) {
                float* fo = (float*)outp;
                *(float2*)&fo[(size_t)r0 * Dm + n] = make_float2(c0, c1);
                *(float2*)&fo[(size_t)r1 * Dm + n] = make_float2(c2, c3);
            } else if (mode == 3) {
                int h = n >> 6, d = n & 63;
                int b0i = r0 >> 11, s0 = r0 & (Ssz - 1);
                int b1i = r1 >> 11, s1 = r1 & (Ssz - 1);
                __half* vo = (__half*)outp;
                vo[((size_t)((b0i*Hn + h)*DKk + d    ))*Ssz + s0] = __float2half_rn(c0);
                vo[((size_t)((b0i*Hn + h)*DKk + d + 1))*Ssz + s0] = __float2half_rn(c1);
                vo[((size_t)((b1i*Hn + h)*DKk + d    ))*Ssz + s1] = __float2half_rn(c2);
                vo[((size_t)((b1i*Hn + h)*DKk + d + 1))*Ssz + s1] = __float2half_rn(c3);
            } else {
                float sc = (mode == 1) ? (0.125f * 1.4426950408889634f) : 1.0f;
                int h = n >> 6, d = n & 63;
                int b0i = r0 >> 11, s0 = r0 & (Ssz - 1);
                int b1i = r1 >> 11, s1 = r1 & (Ssz - 1);
                __half* ho = (__half*)outp;
                *(__half2*)&ho[((size_t)((b0i*Hn + h)*Ssz + s0))*DKk + d] =
                    __floats2half2_rn(c0 * sc, c1 * sc);
                *(__half2*)&ho[((size_t)((b1i*Hn + h)*Ssz + s1))*DKk + d] =
                    __floats2half2_rn(c2 * sc, c3 * sc);
            }
        }
    }
}

__global__ __launch_bounds__(256, 2) void gemm_qkv_f16(const float* __restrict__ bq,
                                                       const float* __restrict__ bk,
                                                       const float* __restrict__ bv)
{
    if (blockIdx.z == 0)      gemm_f16_body(g_Xq, g_Wq, bq, g_Q,  1);
    else if (blockIdx.z == 1) gemm_f16_body(g_Xk, g_Wk, bk, g_K,  2);
    else                      gemm_f16_body(g_Xv, g_Wv, bv, g_Vt, 3);
}

__global__ __launch_bounds__(256, 2) void gemm_out_f16(const float* __restrict__ bo,
                                                       float* __restrict__ out)
{
    gemm_f16_body(g_attn, g_Wo, bo, out, 0);
}

// ---------------------------------------------------------------------------
// f32 -> fp16 RN conversion of GEMM inputs
// ---------------------------------------------------------------------------
__global__ __launch_bounds__(256) void conv_x3(const float* __restrict__ xq,
                                               const float* __restrict__ xk,
                                               const float* __restrict__ xv)
{
    const float* s; __half* d;
    if (blockIdx.z == 0)      { s = xq; d = g_Xq; }
    else if (blockIdx.z == 1) { s = xk; d = g_Xk; }
    else                      { s = xv; d = g_Xv; }
    int i = blockIdx.x * blockDim.x + threadIdx.x;
    float4 v = ((const float4*)s)[i];
    __half2 h0 = __floats2half2_rn(v.x, v.y);
    __half2 h1 = __floats2half2_rn(v.z, v.w);
    uint2 o = { *(uint32_t*)&h0, *(uint32_t*)&h1 };
    *(uint2*)&d[(size_t)i * 4] = o;
}

__global__ __launch_bounds__(256) void conv_w4(const float* __restrict__ wq,
                                               const float* __restrict__ wk,
                                               const float* __restrict__ wv,
                                               const float* __restrict__ wo)
{
    const float* s; __half* d;
    if (blockIdx.z == 0)      { s = wq; d = g_Wq; }
    else if (blockIdx.z == 1) { s = wk; d = g_Wk; }
    else if (blockIdx.z == 2) { s = wv; d = g_Wv; }
    else                      { s = wo; d = g_Wo; }
    int i = blockIdx.x * blockDim.x + threadIdx.x;
    float4 v = ((const float4*)s)[i];
    __half2 h0 = __floats2half2_rn(v.x, v.y);
    __half2 h1 = __floats2half2_rn(v.z, v.w);
    uint2 o = { *(uint32_t*)&h0, *(uint32_t*)&h1 };
    *(uint2*)&d[(size_t)i * 4] = o;
}

// ---------------------------------------------------------------------------
// Flash attention, fp16 mma, register-resident P, ldmatrix fragment loads.
// CTA = 128 q-rows x bh, 8 warps, warp owns 16 rows.
// ---------------------------------------------------------------------------
#define LDKH 72
#define KTILE_H (64 * LDKH)
#define ATT_SMEM (4 * KTILE_H * 2)   // K x2, V x2 = 36864 B

__global__ __launch_bounds__(256, 2) void attn_f16_kernel()
{
    extern __shared__ __half smh[];
    __half* Kbuf[2] = { smh,               smh + KTILE_H };
    __half* Vbuf[2] = { smh + 2*KTILE_H,   smh + 3*KTILE_H };

    const int bh = blockIdx.y;
    const int qb = blockIdx.x * 128;
    const int tid = threadIdx.x;
    const int lane = tid & 31, w = tid >> 5;

    const int lrow16 = lane & 15;
    const int lhi    = lane >> 4;
    const int bsub   = lane & 7;
    const int bhi8   = (lane >> 3) & 1;
    const int bnt    = lane >> 4;

    const __half* Qb  = g_Q  + (size_t)bh * Ssz * DKk;
    const __half* Kbp = g_K  + (size_t)bh * Ssz * DKk;
    const __half* Vtp = g_Vt + (size_t)bh * DKk * Ssz;

    // ---- stage Q tile (128 rows) into smem, grab fragments via ldmatrix ---
#pragma unroll
    for (int i = 0; i < 4; i++) {
        int idx = i * 256 + tid;
        int r = idx >> 3, c = idx & 7;
        cp_async16(smem_u32(&smh[r * LDKH + c * 8]),
                   Qb + (size_t)(qb + r) * DKk + c * 8);
    }
    CP_COMMIT();
    CP_WAIT0();
    __syncthreads();

    uint32_t qfr[4][4];
    {
        const __half* pq = &smh[(w*16 + lrow16) * LDKH + lhi*8];
#pragma unroll
        for (int kk = 0; kk < 4; kk++)
            ldsm4(qfr[kk], smem_u32(pq + kk*16));
    }
    __syncthreads();   // smem free for K/V pipeline

    auto issue_kv = [&](int kt, int bufi) {
        const int base = kt * 64;
        __half* kd = Kbuf[bufi];
        __half* vd = Vbuf[bufi];
#pragma unroll
        for (int i = 0; i < 2; i++) {
            int idx = i * 256 + tid;
            int r = idx >> 3, c = idx & 7;
            cp_async16(smem_u32(&kd[r * LDKH + c * 8]),
                       Kbp + (size_t)(base + r) * DKk + c * 8);
            cp_async16(smem_u32(&vd[r * LDKH + c * 8]),
                       Vtp + (size_t)r * Ssz + base + c * 8);
        }
        CP_COMMIT();
    };

    float oacc[8][4];
#pragma unroll
    for (int nt = 0; nt < 8; nt++)
#pragma unroll
        for (int k = 0; k < 4; k++) oacc[nt][k] = 0.f;
    float mA = -1e30f, mB = -1e30f, lA = 0.f, lB = 0.f;

    const int NT = Ssz / 64;
    issue_kv(0, 0);

    for (int kt = 0; kt < NT; kt++) {
        const int buf = kt & 1;
        if (kt + 1 < NT) {
            issue_kv(kt + 1, buf ^ 1);
            CP_WAIT1();
        } else {
            CP_WAIT0();
        }
        __syncthreads();

        const __half* Ks = Kbuf[buf];
        const __half* Vs = Vbuf[buf];

        // ---- S = Q K^T : ldmatrix.x4 serves two n-tiles per call ----
        float sacc[8][4];
#pragma unroll
        for (int nt = 0; nt < 8; nt++)
#pragma unroll
            for (int k = 0; k < 4; k++) sacc[nt][k] = 0.f;
#pragma unroll
        for (int ntp = 0; ntp < 4; ntp++) {
            const __half* pb = &Ks[(ntp*16 + bnt*8 + bsub) * LDKH + bhi8*8];
#pragma unroll
            for (int kk = 0; kk < 4; kk++) {
                uint32_t bb[4];
                ldsm4(bb, smem_u32(pb + kk*16));
                mma_f16(sacc[2*ntp],     qfr[kk], bb[0], bb[1]);
                mma_f16(sacc[2*ntp + 1], qfr[kk], bb[2], bb[3]);
            }
        }

        // ---- online softmax (base 2), P packed to registers ----
        float mtA = -1e30f, mtB = -1e30f;
#pragma unroll
        for (int nt = 0; nt < 8; nt++) {
            mtA = fmaxf(mtA, fmaxf(sacc[nt][0], sacc[nt][1]));
            mtB = fmaxf(mtB, fmaxf(sacc[nt][2], sacc[nt][3]));
        }
        mtA = fmaxf(mtA, __shfl_xor_sync(0xffffffffu, mtA, 1));
        mtA = fmaxf(mtA, __shfl_xor_sync(0xffffffffu, mtA, 2));
        mtB = fmaxf(mtB, __shfl_xor_sync(0xffffffffu, mtB, 1));
        mtB = fmaxf(mtB, __shfl_xor_sync(0xffffffffu, mtB, 2));

        float mnA = fmaxf(mA, mtA), mnB = fmaxf(mB, mtB);
        float corrA = exp2f(mA - mnA), corrB = exp2f(mB - mnB);
        mA = mnA; mB = mnB;

        float sA = 0.f, sB = 0.f;
        uint32_t pA[8], pB[8];
#pragma unroll
        for (int nt = 0; nt < 8; nt++) {
            float p0 = exp2f(sacc[nt][0] - mA);
            float p1 = exp2f(sacc[nt][1] - mA);
            float p2 = exp2f(sacc[nt][2] - mB);
            float p3 = exp2f(sacc[nt][3] - mB);
            sA += p0 + p1;
            sB += p2 + p3;
            pA[nt] = packh2(p0, p1);
            pB[nt] = packh2(p2, p3);
        }
        sA += __shfl_xor_sync(0xffffffffu, sA, 1);
        sA += __shfl_xor_sync(0xffffffffu, sA, 2);
        sB += __shfl_xor_sync(0xffffffffu, sB, 1);
        sB += __shfl_xor_sync(0xffffffffu, sB, 2);
        lA = lA * corrA + sA;
        lB = lB * corrB + sB;

#pragma unroll
        for (int nt = 0; nt < 8; nt++) {
            oacc[nt][0] *= corrA; oacc[nt][1] *= corrA;
            oacc[nt][2] *= corrB; oacc[nt][3] *= corrB;
        }

        // ---- O += P * V : A-frags from registers, B via ldmatrix ----
#pragma unroll
        for (int ntp = 0; ntp < 4; ntp++) {
            const __half* pb = &Vs[(ntp*16 + bnt*8 + bsub) * LDKH + bhi8*8];
#pragma unroll
            for (int kk = 0; kk < 4; kk++) {
                uint32_t bb[4];
                ldsm4(bb, smem_u32(pb + kk*16));
                uint32_t afr[4] = { pA[2*kk], pB[2*kk], pA[2*kk + 1], pB[2*kk + 1] };
                mma_f16(oacc[2*ntp],     afr, bb[0], bb[1]);
                mma_f16(oacc[2*ntp + 1], afr, bb[2], bb[3]);
            }
        }
        __syncthreads();
    }

    // ---- epilogue: normalize, fp16 RN, write g_attn -----------------------
    const int g = lane >> 2, q = lane & 3;
    float invA = 1.f / lA, invB = 1.f / lB;
    int b = bh >> 4, h = bh & 15;
    int row0 = qb + w * 16 + g;
    int row1 = row0 + 8;
#pragma unroll
    for (int nt = 0; nt < 8; nt++) {
        int col = h * DKk + nt * 8 + q * 2;
        *(__half2*)&g_attn[(size_t)(b * Ssz + row0) * Dm + col] =
            __floats2half2_rn(oacc[nt][0] * invA, oacc[nt][1] * invA);
        *(__half2*)&g_attn[(size_t)(b * Ssz + row1) * Dm + col] =
            __floats2half2_rn(oacc[nt][2] * invB, oacc[nt][3] * invB);
    }
}

// ---------------------------------------------------------------------------
extern "C" void kernel_launch(void* const* d_in, const int* in_sizes, int n_in,
                              void* d_out, int out_size)
{
    const float* query = (const float*)d_in[0];
    const float* key_  = (const float*)d_in[1];
    const float* value = (const float*)d_in[2];
    const float* w_q   = (const float*)d_in[3];
    const float* b_q   = (const float*)d_in[4];
    const float* w_k   = (const float*)d_in[5];
    const float* b_k   = (const float*)d_in[6];
    const float* w_v   = (const float*)d_in[7];
    const float* b_v   = (const float*)d_in[8];
    const float* w_o   = (const float*)d_in[9];
    const float* b_o   = (const float*)d_in[10];
    float* out = (float*)d_out;

    cudaFuncSetAttribute(gemm_qkv_f16, cudaFuncAttributeMaxDynamicSharedMemorySize, GEMM_SMEM_BYTES);
    cudaFuncSetAttribute(gemm_out_f16, cudaFuncAttributeMaxDynamicSharedMemorySize, GEMM_SMEM_BYTES);
    cudaFuncSetAttribute(attn_f16_kernel, cudaFuncAttributeMaxDynamicSharedMemorySize, ATT_SMEM);

    const int nX4 = Mrows * Dm / 4;
    const int nW4 = Dm * Dm / 4;

    conv_x3<<<dim3(nX4 / 256, 1, 3), 256>>>(query, key_, value);
    conv_w4<<<dim3(nW4 / 256, 1, 4), 256>>>(w_q, w_k, w_v, w_o);

    gemm_qkv_f16<<<dim3(8, 64, 3), 256, GEMM_SMEM_BYTES>>>(b_q, b_k, b_v);

    attn_f16_kernel<<<dim3(16, 64), 256, ATT_SMEM>>>();

    gemm_out_f16<<<dim3(8, 64), 256, GEMM_SMEM_BYTES>>>(b_o, out);
}

// round 11
// speedup vs baseline: 2.3695x; 1.0423x over previous
#include <cuda_runtime.h>
#include <cuda_fp16.h>
#include <cstdint>

// Problem constants
#define Bsz 4
#define Ssz 2048
#define Hn  16
#define DKk 64
#define Dm  1024
#define Mrows (Bsz*Ssz)   // 8192

// ---------------- scratch (__device__ globals, fp16) ------------------------
__device__ __align__(1024) __half g_Xq[(size_t)Mrows*Dm];
__device__ __align__(1024) __half g_Xk[(size_t)Mrows*Dm];
__device__ __align__(1024) __half g_Xv[(size_t)Mrows*Dm];
__device__ __align__(1024) __half g_Wq[(size_t)Dm*Dm];
__device__ __align__(1024) __half g_Wk[(size_t)Dm*Dm];
__device__ __align__(1024) __half g_Wv[(size_t)Dm*Dm];
__device__ __align__(1024) __half g_Wo[(size_t)Dm*Dm];
__device__ __align__(1024) __half g_Q[(size_t)Bsz*Hn*Ssz*DKk];    // [b,h,s,d], pre-scaled log2e/8
__device__ __align__(1024) __half g_K[(size_t)Bsz*Hn*Ssz*DKk];    // [b,h,s,d]
__device__ __align__(1024) __half g_Vt[(size_t)Bsz*Hn*DKk*Ssz];   // [b,h,d,s]  TRANSPOSED
__device__ __align__(1024) __half g_attn[(size_t)Mrows*Dm];       // [B*S, D]

// ---------------- helpers ----------------------------------------------------
__device__ __forceinline__ uint32_t smem_u32(const void* p) {
    uint32_t a;
    asm("{ .reg .u64 t; cvta.to.shared.u64 t, %1; cvt.u32.u64 %0, t; }" : "=r"(a) : "l"(p));
    return a;
}
__device__ __forceinline__ void cp_async16(uint32_t dst, const void* src) {
    asm volatile("cp.async.cg.shared.global [%0], [%1], 16;" :: "r"(dst), "l"(src));
}
#define CP_COMMIT() asm volatile("cp.async.commit_group;" ::: "memory")
#define CP_WAIT0()  asm volatile("cp.async.wait_group 0;" ::: "memory")
#define CP_WAIT1()  asm volatile("cp.async.wait_group 1;" ::: "memory")

__device__ __forceinline__ void mma_f16(float* c, const uint32_t* a, uint32_t b0, uint32_t b1) {
    asm volatile(
        "mma.sync.aligned.m16n8k16.row.col.f32.f16.f16.f32 "
        "{%0,%1,%2,%3}, {%4,%5,%6,%7}, {%8,%9}, {%0,%1,%2,%3};"
        : "+f"(c[0]), "+f"(c[1]), "+f"(c[2]), "+f"(c[3])
        : "r"(a[0]), "r"(a[1]), "r"(a[2]), "r"(a[3]), "r"(b0), "r"(b1));
}
__device__ __forceinline__ void ldsm4(uint32_t* r, uint32_t addr) {
    asm volatile("ldmatrix.sync.aligned.m8n8.x4.shared.b16 {%0,%1,%2,%3}, [%4];"
        : "=r"(r[0]), "=r"(r[1]), "=r"(r[2]), "=r"(r[3]) : "r"(addr));
}

// ---------------------------------------------------------------------------
// fp16 NT GEMM with ldmatrix fragment loads, 3-stage cp.async,
// ONE barrier per k-tile (issue happens after the top sync, so the old
// bottom barrier was redundant).
// ---------------------------------------------------------------------------
#define LDH 40
#define GEMM_SMEM_BYTES (6 * 128 * LDH * 2)   // 61440 B

__device__ __forceinline__ void gemm_f16_body(const __half* __restrict__ X,
                                              const __half* __restrict__ W,
                                              const float* __restrict__ bias,
                                              void* __restrict__ outp,
                                              int mode)
{
    extern __shared__ __half smh[];
    __half* Abuf[3] = { smh,               smh + 128*LDH,     smh + 2*128*LDH };
    __half* Bbuf[3] = { smh + 3*128*LDH,   smh + 4*128*LDH,   smh + 5*128*LDH };

    const int tid  = threadIdx.x;
    const int lane = tid & 31, wid = tid >> 5;
    const int wm   = wid >> 2, wn = wid & 3;
    const int g    = lane >> 2, q = lane & 3;
    const int bm   = blockIdx.y * 128;
    const int bn   = blockIdx.x * 128;

    const int lrow16 = lane & 15;
    const int lhi    = lane >> 4;
    const int bsub   = lane & 7;
    const int bhi8   = (lane >> 3) & 1;
    const int bnt    = lane >> 4;

    // per-buffer fragment base addresses (bytes)
    uint32_t abase[3], bbase[3];
    {
        uint32_t aoff = ((wm*64 + lrow16) * LDH + lhi*8) * 2;
        uint32_t boff = ((wn*32 + bnt*8 + bsub) * LDH + bhi8*8) * 2;
#pragma unroll
        for (int s = 0; s < 3; s++) {
            abase[s] = smem_u32(Abuf[s]) + aoff;
            bbase[s] = smem_u32(Bbuf[s]) + boff;
        }
    }

    float acc[4][4][4];
#pragma unroll
    for (int i = 0; i < 4; i++)
#pragma unroll
        for (int j = 0; j < 4; j++)
#pragma unroll
            for (int k = 0; k < 4; k++) acc[i][j][k] = 0.f;

    auto issue_tile = [&](int kt, int buf) {
#pragma unroll
        for (int i = 0; i < 2; i++) {
            int idx = i * 256 + tid;
            int r = idx >> 2, c = idx & 3;
            cp_async16(smem_u32(&Abuf[buf][r * LDH + c * 8]),
                       X + (size_t)(bm + r) * Dm + kt * 32 + c * 8);
        }
#pragma unroll
        for (int i = 0; i < 2; i++) {
            int idx = i * 256 + tid;
            int r = idx >> 2, c = idx & 3;
            cp_async16(smem_u32(&Bbuf[buf][r * LDH + c * 8]),
                       W + (size_t)(bn + r) * Dm + kt * 32 + c * 8);
        }
        CP_COMMIT();
    };

    const int NT = Dm / 32;
    issue_tile(0, 0);
    issue_tile(1, 1);

    int buf = 0;
    for (int kt = 0; kt < NT; kt++) {
        if (kt + 1 < NT) { CP_WAIT1(); } else { CP_WAIT0(); }
        __syncthreads();                 // single barrier per tile
        if (kt + 2 < NT) {
            int nb = buf + 2; if (nb >= 3) nb -= 3;
            issue_tile(kt + 2, nb);
        }

        uint32_t ab = abase[buf], bb_ = bbase[buf];
#pragma unroll
        for (int kk = 0; kk < 2; kk++) {
            uint32_t afr[4][4], bfr[2][4];
#pragma unroll
            for (int mt = 0; mt < 4; mt++)
                ldsm4(afr[mt], ab + kk*32 + mt * (16 * LDH * 2));
#pragma unroll
            for (int ntp = 0; ntp < 2; ntp++)
                ldsm4(bfr[ntp], bb_ + kk*32 + ntp * (16 * LDH * 2));
#pragma unroll
            for (int mt = 0; mt < 4; mt++)
#pragma unroll
                for (int nt = 0; nt < 4; nt++)
                    mma_f16(acc[mt][nt], afr[mt],
                            bfr[nt >> 1][(nt & 1) * 2], bfr[nt >> 1][(nt & 1) * 2 + 1]);
        }
        buf = buf + 1; if (buf >= 3) buf = 0;
    }
    __syncthreads();   // protect final buffers until all reads done (epilogue next)

#pragma unroll
    for (int mt = 0; mt < 4; mt++) {
        int r0 = bm + wm * 64 + mt * 16 + g;
        int r1 = r0 + 8;
#pragma unroll
        for (int nt = 0; nt < 4; nt++) {
            int n = bn + wn * 32 + nt * 8 + q * 2;
            float bn0 = bias[n], bn1 = bias[n + 1];
            float c0 = acc[mt][nt][0] + bn0, c1 = acc[mt][nt][1] + bn1;
            float c2 = acc[mt][nt][2] + bn0, c3 = acc[mt][nt][3] + bn1;
            if (mode == 0) {
                float* fo = (float*)outp;
                *(float2*)&fo[(size_t)r0 * Dm + n] = make_float2(c0, c1);
                *(float2*)&fo[(size_t)r1 * Dm + n] = make_float2(c2, c3);
            } else if (mode == 3) {
                int h = n >> 6, d = n & 63;
                int b0i = r0 >> 11, s0 = r0 & (Ssz - 1);
                int b1i = r1 >> 11, s1 = r1 & (Ssz - 1);
                __half* vo = (__half*)outp;
                vo[((size_t)((b0i*Hn + h)*DKk + d    ))*Ssz + s0] = __float2half_rn(c0);
                vo[((size_t)((b0i*Hn + h)*DKk + d + 1))*Ssz + s0] = __float2half_rn(c1);
                vo[((size_t)((b1i*Hn + h)*DKk + d    ))*Ssz + s1] = __float2half_rn(c2);
                vo[((size_t)((b1i*Hn + h)*DKk + d + 1))*Ssz + s1] = __float2half_rn(c3);
            } else {
                float sc = (mode == 1) ? (0.125f * 1.4426950408889634f) : 1.0f;
                int h = n >> 6, d = n & 63;
                int b0i = r0 >> 11, s0 = r0 & (Ssz - 1);
                int b1i = r1 >> 11, s1 = r1 & (Ssz - 1);
                __half* ho = (__half*)outp;
                *(__half2*)&ho[((size_t)((b0i*Hn + h)*Ssz + s0))*DKk + d] =
                    __floats2half2_rn(c0 * sc, c1 * sc);
                *(__half2*)&ho[((size_t)((b1i*Hn + h)*Ssz + s1))*DKk + d] =
                    __floats2half2_rn(c2 * sc, c3 * sc);
            }
        }
    }
}

__global__ __launch_bounds__(256, 2) void gemm_qkv_f16(const float* __restrict__ bq,
                                                       const float* __restrict__ bk,
                                                       const float* __restrict__ bv)
{
    if (blockIdx.z == 0)      gemm_f16_body(g_Xq, g_Wq, bq, g_Q,  1);
    else if (blockIdx.z == 1) gemm_f16_body(g_Xk, g_Wk, bk, g_K,  2);
    else                      gemm_f16_body(g_Xv, g_Wv, bv, g_Vt, 3);
}

__global__ __launch_bounds__(256, 2) void gemm_out_f16(const float* __restrict__ bo,
                                                       float* __restrict__ out)
{
    gemm_f16_body(g_attn, g_Wo, bo, out, 0);
}

// ---------------------------------------------------------------------------
// f32 -> fp16 RN conversion of GEMM inputs
// ---------------------------------------------------------------------------
__global__ __launch_bounds__(256) void conv_x3(const float* __restrict__ xq,
                                               const float* __restrict__ xk,
                                               const float* __restrict__ xv)
{
    const float* s; __half* d;
    if (blockIdx.z == 0)      { s = xq; d = g_Xq; }
    else if (blockIdx.z == 1) { s = xk; d = g_Xk; }
    else                      { s = xv; d = g_Xv; }
    int i = blockIdx.x * blockDim.x + threadIdx.x;
    float4 v = ((const float4*)s)[i];
    __half2 h0 = __floats2half2_rn(v.x, v.y);
    __half2 h1 = __floats2half2_rn(v.z, v.w);
    uint2 o = { *(uint32_t*)&h0, *(uint32_t*)&h1 };
    *(uint2*)&d[(size_t)i * 4] = o;
}

__global__ __launch_bounds__(256) void conv_w4(const float* __restrict__ wq,
                                               const float* __restrict__ wk,
                                               const float* __restrict__ wv,
                                               const float* __restrict__ wo)
{
    const float* s; __half* d;
    if (blockIdx.z == 0)      { s = wq; d = g_Wq; }
    else if (blockIdx.z == 1) { s = wk; d = g_Wk; }
    else if (blockIdx.z == 2) { s = wv; d = g_Wv; }
    else                      { s = wo; d = g_Wo; }
    int i = blockIdx.x * blockDim.x + threadIdx.x;
    float4 v = ((const float4*)s)[i];
    __half2 h0 = __floats2half2_rn(v.x, v.y);
    __half2 h1 = __floats2half2_rn(v.z, v.w);
    uint2 o = { *(uint32_t*)&h0, *(uint32_t*)&h1 };
    *(uint2*)&d[(size_t)i * 4] = o;
}

// ---------------------------------------------------------------------------
// Flash attention, fp16 mma, register-resident P, ldmatrix, half2 exp2.
// CTA = 128 q-rows x bh, 8 warps, warp owns 16 rows.
// One barrier per tile: wait -> sync -> issue(next) -> compute.
// ---------------------------------------------------------------------------
#define LDKH 72
#define KTILE_H (64 * LDKH)
#define ATT_SMEM (4 * KTILE_H * 2)   // K x2, V x2 = 36864 B

__global__ __launch_bounds__(256, 2) void attn_f16_kernel()
{
    extern __shared__ __half smh[];
    __half* Kbuf[2] = { smh,               smh + KTILE_H };
    __half* Vbuf[2] = { smh + 2*KTILE_H,   smh + 3*KTILE_H };

    const int bh = blockIdx.y;
    const int qb = blockIdx.x * 128;
    const int tid = threadIdx.x;
    const int lane = tid & 31, w = tid >> 5;

    const int lrow16 = lane & 15;
    const int lhi    = lane >> 4;
    const int bsub   = lane & 7;
    const int bhi8   = (lane >> 3) & 1;
    const int bnt    = lane >> 4;

    const __half* Qb  = g_Q  + (size_t)bh * Ssz * DKk;
    const __half* Kbp = g_K  + (size_t)bh * Ssz * DKk;
    const __half* Vtp = g_Vt + (size_t)bh * DKk * Ssz;

    // ---- stage Q tile into smem, grab fragments via ldmatrix --------------
#pragma unroll
    for (int i = 0; i < 4; i++) {
        int idx = i * 256 + tid;
        int r = idx >> 3, c = idx & 7;
        cp_async16(smem_u32(&smh[r * LDKH + c * 8]),
                   Qb + (size_t)(qb + r) * DKk + c * 8);
    }
    CP_COMMIT();
    CP_WAIT0();
    __syncthreads();

    uint32_t qfr[4][4];
    {
        const __half* pq = &smh[(w*16 + lrow16) * LDKH + lhi*8];
#pragma unroll
        for (int kk = 0; kk < 4; kk++)
            ldsm4(qfr[kk], smem_u32(pq + kk*16));
    }
    __syncthreads();   // smem free for K/V pipeline

    // per-buffer fragment base addresses (bytes)
    uint32_t kfb[2], vfb[2];
    {
        uint32_t b0 = smem_u32(smh);
        uint32_t off = ((bnt*8 + bsub) * LDKH + bhi8*8) * 2;
        kfb[0] = b0 + off;
        kfb[1] = b0 + KTILE_H*2 + off;
        vfb[0] = b0 + 2*KTILE_H*2 + off;
        vfb[1] = b0 + 3*KTILE_H*2 + off;
    }

    auto issue_kv = [&](int kt, int bufi) {
        const int base = kt * 64;
        __half* kd = Kbuf[bufi];
        __half* vd = Vbuf[bufi];
#pragma unroll
        for (int i = 0; i < 2; i++) {
            int idx = i * 256 + tid;
            int r = idx >> 3, c = idx & 7;
            cp_async16(smem_u32(&kd[r * LDKH + c * 8]),
                       Kbp + (size_t)(base + r) * DKk + c * 8);
            cp_async16(smem_u32(&vd[r * LDKH + c * 8]),
                       Vtp + (size_t)r * Ssz + base + c * 8);
        }
        CP_COMMIT();
    };

    float oacc[8][4];
#pragma unroll
    for (int nt = 0; nt < 8; nt++)
#pragma unroll
        for (int k = 0; k < 4; k++) oacc[nt][k] = 0.f;
    float mA = -1e30f, mB = -1e30f, lA = 0.f, lB = 0.f;

    const int NT = Ssz / 64;
    issue_kv(0, 0);

    for (int kt = 0; kt < NT; kt++) {
        const int buf = kt & 1;
        CP_WAIT0();          // tile kt resident
        __syncthreads();     // also: all reads of buf^1 (tile kt-1) finished
        if (kt + 1 < NT) issue_kv(kt + 1, buf ^ 1);

        // ---- S = Q K^T ----
        float sacc[8][4];
#pragma unroll
        for (int nt = 0; nt < 8; nt++)
#pragma unroll
            for (int k = 0; k < 4; k++) sacc[nt][k] = 0.f;
        uint32_t kb = kfb[buf];
#pragma unroll
        for (int ntp = 0; ntp < 4; ntp++) {
#pragma unroll
            for (int kk = 0; kk < 4; kk++) {
                uint32_t bb[4];
                ldsm4(bb, kb + ntp * (16 * LDKH * 2) + kk * 32);
                mma_f16(sacc[2*ntp],     qfr[kk], bb[0], bb[1]);
                mma_f16(sacc[2*ntp + 1], qfr[kk], bb[2], bb[3]);
            }
        }

        // ---- online softmax (base 2), half2 exp2, P packed in registers ---
        float mtA = -1e30f, mtB = -1e30f;
#pragma unroll
        for (int nt = 0; nt < 8; nt++) {
            mtA = fmaxf(mtA, fmaxf(sacc[nt][0], sacc[nt][1]));
            mtB = fmaxf(mtB, fmaxf(sacc[nt][2], sacc[nt][3]));
        }
        mtA = fmaxf(mtA, __shfl_xor_sync(0xffffffffu, mtA, 1));
        mtA = fmaxf(mtA, __shfl_xor_sync(0xffffffffu, mtA, 2));
        mtB = fmaxf(mtB, __shfl_xor_sync(0xffffffffu, mtB, 1));
        mtB = fmaxf(mtB, __shfl_xor_sync(0xffffffffu, mtB, 2));

        float mnA = fmaxf(mA, mtA), mnB = fmaxf(mB, mtB);
        float corrA = exp2f(mA - mnA), corrB = exp2f(mB - mnB);
        mA = mnA; mB = mnB;

        float sA = 0.f, sB = 0.f;
        uint32_t pA[8], pB[8];
#pragma unroll
        for (int nt = 0; nt < 8; nt++) {
            __half2 hdA = __floats2half2_rn(sacc[nt][0] - mA, sacc[nt][1] - mA);
            __half2 hdB = __floats2half2_rn(sacc[nt][2] - mB, sacc[nt][3] - mB);
            __half2 epA = h2exp2(hdA);
            __half2 epB = h2exp2(hdB);
            pA[nt] = *(uint32_t*)&epA;
            pB[nt] = *(uint32_t*)&epB;
            float2 fA = __half22float2(epA);
            float2 fB = __half22float2(epB);
            sA += fA.x + fA.y;
            sB += fB.x + fB.y;
        }
        sA += __shfl_xor_sync(0xffffffffu, sA, 1);
        sA += __shfl_xor_sync(0xffffffffu, sA, 2);
        sB += __shfl_xor_sync(0xffffffffu, sB, 1);
        sB += __shfl_xor_sync(0xffffffffu, sB, 2);
        lA = lA * corrA + sA;
        lB = lB * corrB + sB;

#pragma unroll
        for (int nt = 0; nt < 8; nt++) {
            oacc[nt][0] *= corrA; oacc[nt][1] *= corrA;
            oacc[nt][2] *= corrB; oacc[nt][3] *= corrB;
        }

        // ---- O += P * V ----
        uint32_t vb = vfb[buf];
#pragma unroll
        for (int ntp = 0; ntp < 4; ntp++) {
#pragma unroll
            for (int kk = 0; kk < 4; kk++) {
                uint32_t bb[4];
                ldsm4(bb, vb + ntp * (16 * LDKH * 2) + kk * 32);
                uint32_t afr[4] = { pA[2*kk], pB[2*kk], pA[2*kk + 1], pB[2*kk + 1] };
                mma_f16(oacc[2*ntp],     afr, bb[0], bb[1]);
                mma_f16(oacc[2*ntp + 1], afr, bb[2], bb[3]);
            }
        }
    }

    // ---- epilogue: normalize, fp16 RN, write g_attn -----------------------
    const int g = lane >> 2, q = lane & 3;
    float invA = 1.f / lA, invB = 1.f / lB;
    int b = bh >> 4, h = bh & 15;
    int row0 = qb + w * 16 + g;
    int row1 = row0 + 8;
#pragma unroll
    for (int nt = 0; nt < 8; nt++) {
        int col = h * DKk + nt * 8 + q * 2;
        *(__half2*)&g_attn[(size_t)(b * Ssz + row0) * Dm + col] =
            __floats2half2_rn(oacc[nt][0] * invA, oacc[nt][1] * invA);
        *(__half2*)&g_attn[(size_t)(b * Ssz + row1) * Dm + col] =
            __floats2half2_rn(oacc[nt][2] * invB, oacc[nt][3] * invB);
    }
}

// ---------------------------------------------------------------------------
extern "C" void kernel_launch(void* const* d_in, const int* in_sizes, int n_in,
                              void* d_out, int out_size)
{
    const float* query = (const float*)d_in[0];
    const float* key_  = (const float*)d_in[1];
    const float* value = (const float*)d_in[2];
    const float* w_q   = (const float*)d_in[3];
    const float* b_q   = (const float*)d_in[4];
    const float* w_k   = (const float*)d_in[5];
    const float* b_k   = (const float*)d_in[6];
    const float* w_v   = (const float*)d_in[7];
    const float* b_v   = (const float*)d_in[8];
    const float* w_o   = (const float*)d_in[9];
    const float* b_o   = (const float*)d_in[10];
    float* out = (float*)d_out;

    cudaFuncSetAttribute(gemm_qkv_f16, cudaFuncAttributeMaxDynamicSharedMemorySize, GEMM_SMEM_BYTES);
    cudaFuncSetAttribute(gemm_out_f16, cudaFuncAttributeMaxDynamicSharedMemorySize, GEMM_SMEM_BYTES);
    cudaFuncSetAttribute(attn_f16_kernel, cudaFuncAttributeMaxDynamicSharedMemorySize, ATT_SMEM);

    const int nX4 = Mrows * Dm / 4;
    const int nW4 = Dm * Dm / 4;

    conv_x3<<<dim3(nX4 / 256, 1, 3), 256>>>(query, key_, value);
    conv_w4<<<dim3(nW4 / 256, 1, 4), 256>>>(w_q, w_k, w_v, w_o);

    gemm_qkv_f16<<<dim3(8, 64, 3), 256, GEMM_SMEM_BYTES>>>(b_q, b_k, b_v);

    attn_f16_kernel<<<dim3(16, 64), 256, ATT_SMEM>>>();

    gemm_out_f16<<<dim3(8, 64), 256, GEMM_SMEM_BYTES>>>(b_o, out);
}